// round 1
// baseline (speedup 1.0000x reference)
#include <cuda_runtime.h>

namespace {

constexpr int Bb = 64, Nn = 512, Mm = 30, NE = 32;
constexpr int NPAIR = Bb * Nn;        // 32768
constexpr int WARPS = 16;
constexpr int THREADS = WARPS * 32;   // 512
constexpr int GRID = 148;
constexpr unsigned FULLM = 0xffffffffu;

struct Smem {
  // fit weights, re-laid out as (W[p][j], W[p][j+32]) pairs
  float2 wf0p[256 * 32];   // 64 KB
  float2 wf1p[64 * 32];    // 16 KB
  float2 wf2p[64 * 32];    // 16 KB
  float4 sg[WARPS][Mm];    // per-warp Sg tile
  float4 rr[WARPS][Mm];    // per-warp R tile
  float  hbuf[WARPS][2][NE];
  float  dbuf[WARPS][256];
  float  ybuf[WARPS][64];
  float  bf0s[64], bf1s[64], bf2s[64], wf3s[64];
  float  bf3s;
};

__device__ __forceinline__ float tanh_fast(float x) {
  float y;
  asm("tanh.approx.f32 %0, %1;" : "=f"(y) : "f"(x));
  return y;
}
__device__ __forceinline__ float sigmoid_fast(float x) {
  return 0.5f * tanh_fast(0.5f * x) + 0.5f;
}

// One fit layer: NIN inputs (broadcast from smem, float4), 64 outputs,
// lane computes outputs (lane, lane+32) via paired weights.
template <int NIN>
__device__ __forceinline__ void fit_layer(const float2* __restrict__ wp,
                                          const float* __restrict__ bs,
                                          const float4* __restrict__ in,
                                          int lane, float& o0, float& o1) {
  float a0 = bs[lane], a1 = bs[lane + 32];
  float b0 = 0.f, b1 = 0.f;
#pragma unroll 8
  for (int p4 = 0; p4 < NIN / 4; p4++) {
    float4 d4 = in[p4];
    float2 w0 = wp[(p4 * 4 + 0) * 32 + lane];
    float2 w1 = wp[(p4 * 4 + 1) * 32 + lane];
    float2 w2 = wp[(p4 * 4 + 2) * 32 + lane];
    float2 w3 = wp[(p4 * 4 + 3) * 32 + lane];
    if (p4 & 1) {
      b0 += d4.x * w0.x + d4.y * w1.x + d4.z * w2.x + d4.w * w3.x;
      b1 += d4.x * w0.y + d4.y * w1.y + d4.z * w2.y + d4.w * w3.y;
    } else {
      a0 += d4.x * w0.x + d4.y * w1.x + d4.z * w2.x + d4.w * w3.x;
      a1 += d4.x * w0.y + d4.y * w1.y + d4.z * w2.y + d4.w * w3.y;
    }
  }
  o0 = a0 + b0;
  o1 = a1 + b1;
}

}  // namespace

__global__ void __launch_bounds__(THREADS, 1) fused_pair_kernel(
    const float* __restrict__ Sg, const float* __restrict__ R,
    const float* __restrict__ We0, const float* __restrict__ be0,
    const float* __restrict__ We1, const float* __restrict__ be1,
    const float* __restrict__ We2, const float* __restrict__ be2,
    const float* __restrict__ Wf0, const float* __restrict__ bf0,
    const float* __restrict__ Wf1, const float* __restrict__ bf1,
    const float* __restrict__ Wf2, const float* __restrict__ bf2,
    const float* __restrict__ Wf3, const float* __restrict__ bf3,
    float* __restrict__ out) {
  extern __shared__ char smraw[];
  Smem* s = reinterpret_cast<Smem*>(smraw);
  const int tid = threadIdx.x;

  // ---- block-wide weight staging (once per block, reused across ~14 pairs/warp)
  for (int i = tid; i < 256 * 32; i += THREADS) {
    int p = i >> 5, j = i & 31;
    s->wf0p[i] = make_float2(Wf0[p * 64 + j], Wf0[p * 64 + j + 32]);
  }
  for (int i = tid; i < 64 * 32; i += THREADS) {
    int p = i >> 5, j = i & 31;
    s->wf1p[i] = make_float2(Wf1[p * 64 + j], Wf1[p * 64 + j + 32]);
    s->wf2p[i] = make_float2(Wf2[p * 64 + j], Wf2[p * 64 + j + 32]);
  }
  if (tid < 64) {
    s->bf0s[tid] = bf0[tid];
    s->bf1s[tid] = bf1[tid];
    s->bf2s[tid] = bf2[tid];
    s->wf3s[tid] = Wf3[tid];
  }
  if (tid == 0) s->bf3s = bf3[0];

  const int lane = tid & 31, wid = tid >> 5;

  // ---- per-lane register copy of embedding-MLP weight columns
  float we0c[4], we1c[32], we2c[32];
#pragma unroll
  for (int e = 0; e < 4; e++) we0c[e] = We0[e * 32 + lane];
#pragma unroll
  for (int i = 0; i < 32; i++) {
    we1c[i] = We1[i * 32 + lane];
    we2c[i] = We2[i * 32 + lane];
  }
  const float be0v = be0[lane], be1v = be1[lane], be2v = be2[lane];
  __syncthreads();

  const int ak = lane >> 2, al = lane & 3;  // A[k][l] ownership: lane = k*4+l

  for (int pair = blockIdx.x * WARPS + wid; pair < NPAIR; pair += GRID * WARPS) {
    const float4* sgp = reinterpret_cast<const float4*>(Sg) + pair * Mm;
    const float4* rp = reinterpret_cast<const float4*>(R) + pair * Mm;
    if (lane < Mm) {
      s->sg[wid][lane] = sgp[lane];
      s->rr[wid][lane] = rp[lane];
    }
    __syncwarp();

    float bm0 = 0.f, bm1 = 0.f, bm2 = 0.f, bm3 = 0.f, aacc = 0.f;

#pragma unroll 1
    for (int m = 0; m < Mm; m++) {
      float4 x = s->sg[wid][m];
      float h1 = sigmoid_fast(be0v + x.x * we0c[0] + x.y * we0c[1] +
                              x.z * we0c[2] + x.w * we0c[3]);
      s->hbuf[wid][0][lane] = h1;
      __syncwarp();
      {
        const float4* hb = reinterpret_cast<const float4*>(s->hbuf[wid][0]);
        float acc0 = be1v, acc1 = 0.f;
#pragma unroll
        for (int i4 = 0; i4 < 8; i4 += 2) {
          float4 v = hb[i4];
          acc0 += v.x * we1c[4 * i4 + 0] + v.y * we1c[4 * i4 + 1] +
                  v.z * we1c[4 * i4 + 2] + v.w * we1c[4 * i4 + 3];
          float4 w = hb[i4 + 1];
          acc1 += w.x * we1c[4 * i4 + 4] + w.y * we1c[4 * i4 + 5] +
                  w.z * we1c[4 * i4 + 6] + w.w * we1c[4 * i4 + 7];
        }
        float h2 = tanh_fast(acc0 + acc1);
        s->hbuf[wid][1][lane] = h2;
      }
      __syncwarp();
      float g;
      {
        const float4* hb = reinterpret_cast<const float4*>(s->hbuf[wid][1]);
        float acc0 = be2v, acc1 = 0.f;
#pragma unroll
        for (int i4 = 0; i4 < 8; i4 += 2) {
          float4 v = hb[i4];
          acc0 += v.x * we2c[4 * i4 + 0] + v.y * we2c[4 * i4 + 1] +
                  v.z * we2c[4 * i4 + 2] + v.w * we2c[4 * i4 + 3];
          float4 w = hb[i4 + 1];
          acc1 += w.x * we2c[4 * i4 + 4] + w.y * we2c[4 * i4 + 5] +
                  w.z * we2c[4 * i4 + 6] + w.w * we2c[4 * i4 + 7];
        }
        g = acc0 + acc1;  // G[m][lane]
      }
      float4 r = s->rr[wid][m];
      // Bm[l][lane] accumulation
      bm0 += r.x * g;
      bm1 += r.y * g;
      bm2 += r.z * g;
      bm3 += r.w * g;
      // A[k][l] accumulation (lane = k*4+l)
      float gk = __shfl_sync(FULLM, g, ak);
      float rl = (al == 0) ? r.x : (al == 1) ? r.y : (al == 2) ? r.z : r.w;
      aacc += gk * rl;
    }

    // ---- D[k][n] = sum_l A[k][l] * Bm[l][n], lane = n
    {
      float bmv[4] = {bm0, bm1, bm2, bm3};
#pragma unroll
      for (int k = 0; k < 8; k++) {
        float d = 0.f;
#pragma unroll
        for (int l = 0; l < 4; l++) {
          float a = __shfl_sync(FULLM, aacc, k * 4 + l);
          d += a * bmv[l];
        }
        s->dbuf[wid][k * 32 + lane] = d;
      }
    }
    __syncwarp();

    // ---- fit MLP: 256 -> 64 (tanh) -> 64 (sigmoid) -> 64 (tanh) -> 1
    float o0, o1;
    fit_layer<256>(s->wf0p, s->bf0s,
                   reinterpret_cast<const float4*>(s->dbuf[wid]), lane, o0, o1);
    s->ybuf[wid][lane] = tanh_fast(o0);
    s->ybuf[wid][lane + 32] = tanh_fast(o1);
    __syncwarp();

    fit_layer<64>(s->wf1p, s->bf1s,
                  reinterpret_cast<const float4*>(s->ybuf[wid]), lane, o0, o1);
    float y1a = sigmoid_fast(o0), y1b = sigmoid_fast(o1);
    __syncwarp();  // all lanes done reading ybuf before overwrite
    s->ybuf[wid][lane] = y1a;
    s->ybuf[wid][lane + 32] = y1b;
    __syncwarp();

    fit_layer<64>(s->wf2p, s->bf2s,
                  reinterpret_cast<const float4*>(s->ybuf[wid]), lane, o0, o1);
    float y2a = tanh_fast(o0), y2b = tanh_fast(o1);
    __syncwarp();  // all lanes done reading ybuf (pair-loop reuse safety)

    // ---- final 64 -> 1 + warp reduction, accumulate mean into out[b]
    float q = y2a * s->wf3s[lane] + y2b * s->wf3s[lane + 32];
#pragma unroll
    for (int off = 16; off; off >>= 1) q += __shfl_xor_sync(FULLM, q, off);
    if (lane == 0) {
      atomicAdd(out + (pair >> 9), (q + s->bf3s) * (1.0f / (float)Nn));
    }
  }
}

extern "C" void kernel_launch(void* const* d_in, const int* in_sizes, int n_in,
                              void* d_out, int out_size) {
  const float* Sg = (const float*)d_in[0];
  const float* R = (const float*)d_in[1];
  const float* We0 = (const float*)d_in[2];
  const float* be0 = (const float*)d_in[3];
  const float* We1 = (const float*)d_in[4];
  const float* be1 = (const float*)d_in[5];
  const float* We2 = (const float*)d_in[6];
  const float* be2 = (const float*)d_in[7];
  const float* Wf0 = (const float*)d_in[8];
  const float* bf0 = (const float*)d_in[9];
  const float* Wf1 = (const float*)d_in[10];
  const float* bf1 = (const float*)d_in[11];
  const float* Wf2 = (const float*)d_in[12];
  const float* bf2 = (const float*)d_in[13];
  const float* Wf3 = (const float*)d_in[14];
  const float* bf3 = (const float*)d_in[15];
  float* out = (float*)d_out;

  (void)in_sizes;
  (void)n_in;

  cudaFuncSetAttribute(fused_pair_kernel,
                       cudaFuncAttributeMaxDynamicSharedMemorySize,
                       (int)sizeof(Smem));

  // out is poisoned; zero it (memset node is graph-capturable)
  cudaMemsetAsync(out, 0, (size_t)out_size * sizeof(float));

  fused_pair_kernel<<<GRID, THREADS, sizeof(Smem)>>>(
      Sg, R, We0, be0, We1, be1, We2, be2, Wf0, bf0, Wf1, bf1, Wf2, bf2, Wf3,
      bf3, out);
}

// round 2
// speedup vs baseline: 1.1388x; 1.1388x over previous
#include <cuda_runtime.h>

namespace {

constexpr int Bb = 64, Nn = 512, Mm = 30, NE = 32;
constexpr int NPAIR = Bb * Nn;        // 32768
constexpr int NPAIR2 = NPAIR / 2;     // 16384 pair-pairs
constexpr int WARPS = 16;
constexpr int THREADS = WARPS * 32;   // 512
constexpr int GRID = 148;
constexpr unsigned FULLM = 0xffffffffu;

struct Smem {
  // fit weights, re-laid out as (W[p][j], W[p][j+32]) pairs
  float2 wf0p[256 * 32];      // 64 KB
  float2 wf1p[64 * 32];       // 16 KB
  float2 wf2p[64 * 32];       // 16 KB
  float4 sg[WARPS][2][Mm];    // per-warp Sg tiles (2 pairs)
  float4 rr[WARPS][2][Mm];
  float  hbuf[WARPS][2][2][NE];
  float  dbuf[WARPS][2][256];
  float  ybuf[WARPS][2][64];
  float  bf0s[64], bf1s[64], bf2s[64], wf3s[64];
  float  bf3s;
};

__device__ __forceinline__ float tanh_fast(float x) {
  float y;
  asm("tanh.approx.f32 %0, %1;" : "=f"(y) : "f"(x));
  return y;
}
__device__ __forceinline__ float sigmoid_fast(float x) {
  return 0.5f * tanh_fast(0.5f * x) + 0.5f;
}

// One fit layer applied to TWO pairs with shared weight loads.
// Lane computes outputs (lane, lane+32) for both pairs.
template <int NIN>
__device__ __forceinline__ void fit_layer2(const float2* __restrict__ wp,
                                           const float* __restrict__ bs,
                                           const float4* __restrict__ in0,
                                           const float4* __restrict__ in1,
                                           int lane, float o[2][2]) {
  float a00 = bs[lane], a01 = bs[lane + 32];
  float a10 = a00, a11 = a01;  // same biases for pair1
  a10 = bs[lane];
  a11 = bs[lane + 32];
  float s00 = 0.f, s01 = 0.f, s10 = 0.f, s11 = 0.f;
#pragma unroll 4
  for (int p4 = 0; p4 < NIN / 4; p4++) {
    float4 da = in0[p4];
    float4 db = in1[p4];
    float2 w0 = wp[(p4 * 4 + 0) * 32 + lane];
    float2 w1 = wp[(p4 * 4 + 1) * 32 + lane];
    float2 w2 = wp[(p4 * 4 + 2) * 32 + lane];
    float2 w3 = wp[(p4 * 4 + 3) * 32 + lane];
    s00 += da.x * w0.x + da.y * w1.x + da.z * w2.x + da.w * w3.x;
    s01 += da.x * w0.y + da.y * w1.y + da.z * w2.y + da.w * w3.y;
    s10 += db.x * w0.x + db.y * w1.x + db.z * w2.x + db.w * w3.x;
    s11 += db.x * w0.y + db.y * w1.y + db.z * w2.y + db.w * w3.y;
  }
  o[0][0] = a00 + s00;
  o[0][1] = a01 + s01;
  o[1][0] = a10 + s10;
  o[1][1] = a11 + s11;
}

}  // namespace

__global__ void __launch_bounds__(THREADS, 1) fused_pair_kernel(
    const float* __restrict__ Sg, const float* __restrict__ R,
    const float* __restrict__ We0, const float* __restrict__ be0,
    const float* __restrict__ We1, const float* __restrict__ be1,
    const float* __restrict__ We2, const float* __restrict__ be2,
    const float* __restrict__ Wf0, const float* __restrict__ bf0,
    const float* __restrict__ Wf1, const float* __restrict__ bf1,
    const float* __restrict__ Wf2, const float* __restrict__ bf2,
    const float* __restrict__ Wf3, const float* __restrict__ bf3,
    float* __restrict__ out) {
  extern __shared__ char smraw[];
  Smem* s = reinterpret_cast<Smem*>(smraw);
  const int tid = threadIdx.x;

  // ---- block-wide weight staging (once per block)
  for (int i = tid; i < 256 * 32; i += THREADS) {
    int p = i >> 5, j = i & 31;
    s->wf0p[i] = make_float2(Wf0[p * 64 + j], Wf0[p * 64 + j + 32]);
  }
  for (int i = tid; i < 64 * 32; i += THREADS) {
    int p = i >> 5, j = i & 31;
    s->wf1p[i] = make_float2(Wf1[p * 64 + j], Wf1[p * 64 + j + 32]);
    s->wf2p[i] = make_float2(Wf2[p * 64 + j], Wf2[p * 64 + j + 32]);
  }
  if (tid < 64) {
    s->bf0s[tid] = bf0[tid];
    s->bf1s[tid] = bf1[tid];
    s->bf2s[tid] = bf2[tid];
    s->wf3s[tid] = Wf3[tid];
  }
  if (tid == 0) s->bf3s = bf3[0];

  const int lane = tid & 31, wid = tid >> 5;

  // ---- per-lane register copy of embedding-MLP weight columns
  float we0c[4], we1c[32], we2c[32];
#pragma unroll
  for (int e = 0; e < 4; e++) we0c[e] = We0[e * 32 + lane];
#pragma unroll
  for (int i = 0; i < 32; i++) {
    we1c[i] = We1[i * 32 + lane];
    we2c[i] = We2[i * 32 + lane];
  }
  const float be0v = be0[lane], be1v = be1[lane], be2v = be2[lane];
  __syncthreads();

  const int ak = lane >> 2, al = lane & 3;  // A[k][l] ownership: lane = k*4+l

  for (int it = blockIdx.x * WARPS + wid; it < NPAIR2; it += GRID * WARPS) {
    const int pair0 = it * 2;  // pair0, pair0+1 always share the same b
    // stage both pairs' Sg/R tiles
    if (lane < Mm) {
      const float4* sgp = reinterpret_cast<const float4*>(Sg) + pair0 * Mm;
      const float4* rp = reinterpret_cast<const float4*>(R) + pair0 * Mm;
      s->sg[wid][0][lane] = sgp[lane];
      s->sg[wid][1][lane] = sgp[Mm + lane];
      s->rr[wid][0][lane] = rp[lane];
      s->rr[wid][1][lane] = rp[Mm + lane];
    }
    __syncwarp();

    float bm[2][4] = {{0.f, 0.f, 0.f, 0.f}, {0.f, 0.f, 0.f, 0.f}};
    float aacc[2] = {0.f, 0.f};

#pragma unroll 1
    for (int m = 0; m < Mm; m++) {
      // layer 0 (4 -> 32, sigmoid), both pairs
#pragma unroll
      for (int pp = 0; pp < 2; pp++) {
        float4 x = s->sg[wid][pp][m];
        float h1 = sigmoid_fast(be0v + x.x * we0c[0] + x.y * we0c[1] +
                                x.z * we0c[2] + x.w * we0c[3]);
        s->hbuf[wid][pp][0][lane] = h1;
      }
      __syncwarp();
      // layer 1 (32 -> 32, tanh), both pairs
#pragma unroll
      for (int pp = 0; pp < 2; pp++) {
        const float4* hb = reinterpret_cast<const float4*>(s->hbuf[wid][pp][0]);
        float acc0 = be1v, acc1 = 0.f;
#pragma unroll
        for (int i4 = 0; i4 < 8; i4 += 2) {
          float4 v = hb[i4];
          acc0 += v.x * we1c[4 * i4 + 0] + v.y * we1c[4 * i4 + 1] +
                  v.z * we1c[4 * i4 + 2] + v.w * we1c[4 * i4 + 3];
          float4 w = hb[i4 + 1];
          acc1 += w.x * we1c[4 * i4 + 4] + w.y * we1c[4 * i4 + 5] +
                  w.z * we1c[4 * i4 + 6] + w.w * we1c[4 * i4 + 7];
        }
        s->hbuf[wid][pp][1][lane] = tanh_fast(acc0 + acc1);
      }
      __syncwarp();
      // layer 2 (32 -> 32, linear) + bilinear accumulation, both pairs
#pragma unroll
      for (int pp = 0; pp < 2; pp++) {
        const float4* hb = reinterpret_cast<const float4*>(s->hbuf[wid][pp][1]);
        float acc0 = be2v, acc1 = 0.f;
#pragma unroll
        for (int i4 = 0; i4 < 8; i4 += 2) {
          float4 v = hb[i4];
          acc0 += v.x * we2c[4 * i4 + 0] + v.y * we2c[4 * i4 + 1] +
                  v.z * we2c[4 * i4 + 2] + v.w * we2c[4 * i4 + 3];
          float4 w = hb[i4 + 1];
          acc1 += w.x * we2c[4 * i4 + 4] + w.y * we2c[4 * i4 + 5] +
                  w.z * we2c[4 * i4 + 6] + w.w * we2c[4 * i4 + 7];
        }
        float g = acc0 + acc1;  // G[m][lane]
        float4 r = s->rr[wid][pp][m];
        bm[pp][0] += r.x * g;
        bm[pp][1] += r.y * g;
        bm[pp][2] += r.z * g;
        bm[pp][3] += r.w * g;
        float gk = __shfl_sync(FULLM, g, ak);
        float rl = (al == 0) ? r.x : (al == 1) ? r.y : (al == 2) ? r.z : r.w;
        aacc[pp] += gk * rl;
      }
    }

    // ---- D[k][n] = sum_l A[k][l] * Bm[l][n], lane = n (both pairs)
#pragma unroll
    for (int pp = 0; pp < 2; pp++) {
#pragma unroll
      for (int k = 0; k < 8; k++) {
        float d = 0.f;
#pragma unroll
        for (int l = 0; l < 4; l++) {
          float a = __shfl_sync(FULLM, aacc[pp], k * 4 + l);
          d += a * bm[pp][l];
        }
        s->dbuf[wid][pp][k * 32 + lane] = d;
      }
    }
    __syncwarp();

    // ---- fit MLP: 256 -> 64 (tanh) -> 64 (sigmoid) -> 64 (tanh) -> 1
    float o[2][2];
    fit_layer2<256>(s->wf0p, s->bf0s,
                    reinterpret_cast<const float4*>(s->dbuf[wid][0]),
                    reinterpret_cast<const float4*>(s->dbuf[wid][1]), lane, o);
    s->ybuf[wid][0][lane] = tanh_fast(o[0][0]);
    s->ybuf[wid][0][lane + 32] = tanh_fast(o[0][1]);
    s->ybuf[wid][1][lane] = tanh_fast(o[1][0]);
    s->ybuf[wid][1][lane + 32] = tanh_fast(o[1][1]);
    __syncwarp();

    fit_layer2<64>(s->wf1p, s->bf1s,
                   reinterpret_cast<const float4*>(s->ybuf[wid][0]),
                   reinterpret_cast<const float4*>(s->ybuf[wid][1]), lane, o);
    float y00 = sigmoid_fast(o[0][0]), y01 = sigmoid_fast(o[0][1]);
    float y10 = sigmoid_fast(o[1][0]), y11 = sigmoid_fast(o[1][1]);
    __syncwarp();  // all lanes done reading ybuf before overwrite
    s->ybuf[wid][0][lane] = y00;
    s->ybuf[wid][0][lane + 32] = y01;
    s->ybuf[wid][1][lane] = y10;
    s->ybuf[wid][1][lane + 32] = y11;
    __syncwarp();

    fit_layer2<64>(s->wf2p, s->bf2s,
                   reinterpret_cast<const float4*>(s->ybuf[wid][0]),
                   reinterpret_cast<const float4*>(s->ybuf[wid][1]), lane, o);
    __syncwarp();  // all lanes done reading ybuf (loop reuse safety)

    // ---- final 64 -> 1 + warp reduction, accumulate mean into out[b]
    float wl = s->wf3s[lane], wh = s->wf3s[lane + 32];
    float q = tanh_fast(o[0][0]) * wl + tanh_fast(o[0][1]) * wh +
              tanh_fast(o[1][0]) * wl + tanh_fast(o[1][1]) * wh;
#pragma unroll
    for (int off = 16; off; off >>= 1) q += __shfl_xor_sync(FULLM, q, off);
    if (lane == 0) {
      atomicAdd(out + (pair0 >> 9),
                (q + 2.0f * s->bf3s) * (1.0f / (float)Nn));
    }
  }
}

extern "C" void kernel_launch(void* const* d_in, const int* in_sizes, int n_in,
                              void* d_out, int out_size) {
  const float* Sg = (const float*)d_in[0];
  const float* R = (const float*)d_in[1];
  const float* We0 = (const float*)d_in[2];
  const float* be0 = (const float*)d_in[3];
  const float* We1 = (const float*)d_in[4];
  const float* be1 = (const float*)d_in[5];
  const float* We2 = (const float*)d_in[6];
  const float* be2 = (const float*)d_in[7];
  const float* Wf0 = (const float*)d_in[8];
  const float* bf0 = (const float*)d_in[9];
  const float* Wf1 = (const float*)d_in[10];
  const float* bf1 = (const float*)d_in[11];
  const float* Wf2 = (const float*)d_in[12];
  const float* bf2 = (const float*)d_in[13];
  const float* Wf3 = (const float*)d_in[14];
  const float* bf3 = (const float*)d_in[15];
  float* out = (float*)d_out;

  (void)in_sizes;
  (void)n_in;

  cudaFuncSetAttribute(fused_pair_kernel,
                       cudaFuncAttributeMaxDynamicSharedMemorySize,
                       (int)sizeof(Smem));

  cudaMemsetAsync(out, 0, (size_t)out_size * sizeof(float));

  fused_pair_kernel<<<GRID, THREADS, sizeof(Smem)>>>(
      Sg, R, We0, be0, We1, be1, We2, be2, Wf0, bf0, Wf1, bf1, Wf2, bf2, Wf3,
      bf3, out);
}

// round 3
// speedup vs baseline: 1.2640x; 1.1099x over previous
#include <cuda_runtime.h>

namespace {

constexpr int Bb = 64, Nn = 512, Mm = 30, NE = 32;
constexpr int NPAIR = Bb * Nn;        // 32768
constexpr int NPAIR2 = NPAIR / 2;     // 16384 pair-pairs
constexpr int WARPS = 16;
constexpr int THREADS = WARPS * 32;   // 512
constexpr int GRID = 148;
constexpr unsigned FULLM = 0xffffffffu;

typedef unsigned long long ull;

struct Smem {
  // fit weights packed for f32x2: value[p4][j] = (W[4p4+0][j],W[4p4+1][j],W[4p4+2][j],W[4p4+3][j])
  float4 wf0lo[64 * 32];   // 32 KB (outputs j)
  float4 wf0hi[64 * 32];   // 32 KB (outputs j+32)
  float4 wf1lo[16 * 32];   // 8 KB
  float4 wf1hi[16 * 32];   // 8 KB
  float4 wf2lo[16 * 32];   // 8 KB
  float4 wf2hi[16 * 32];   // 8 KB
  float4 sg[WARPS][2][Mm];
  float4 rr[WARPS][2][Mm];
  float  hbuf[WARPS][2][2][NE];
  float  dbuf[WARPS][2][256];
  float  ybuf[WARPS][2][64];
  float  bf0s[64], bf1s[64], bf2s[64], wf3s[64];
  float  bf3s;
};

__device__ __forceinline__ float tanh_fast(float x) {
  float y;
  asm("tanh.approx.f32 %0, %1;" : "=f"(y) : "f"(x));
  return y;
}
__device__ __forceinline__ float sigmoid_fast(float x) {
  return 0.5f * tanh_fast(0.5f * x) + 0.5f;
}

__device__ __forceinline__ ull pack2(float lo, float hi) {
  ull r;
  asm("mov.b64 %0, {%1, %2};" : "=l"(r) : "f"(lo), "f"(hi));
  return r;
}
__device__ __forceinline__ void unpack2(ull v, float& lo, float& hi) {
  asm("mov.b64 {%0, %1}, %2;" : "=f"(lo), "=f"(hi) : "l"(v));
}
__device__ __forceinline__ ull ffma2(ull a, ull b, ull c) {
  ull d;
  asm("fma.rn.f32x2 %0, %1, %2, %3;" : "=l"(d) : "l"(a), "l"(b), "l"(c));
  return d;
}
__device__ __forceinline__ float hsum2(ull v) {
  float a, b;
  unpack2(v, a, b);
  return a + b;
}

// One fit layer for TWO pairs, f32x2-packed over the input index.
// Lane produces outputs (lane, lane+32) for both pairs.
template <int NIN>
__device__ __forceinline__ void fit_layer2(const float4* __restrict__ wlo,
                                           const float4* __restrict__ whi,
                                           const float* __restrict__ bs,
                                           const ulonglong2* __restrict__ in0,
                                           const ulonglong2* __restrict__ in1,
                                           int lane, float o[2][2]) {
  ull a00 = 0, a01 = 0, a10 = 0, a11 = 0;
  ull b00 = 0, b01 = 0, b10 = 0, b11 = 0;
#pragma unroll 8
  for (int p4 = 0; p4 < NIN / 4; p4++) {
    ulonglong2 da = in0[p4];  // broadcast: (d[4p4],d[4p4+1]),(d[4p4+2],d[4p4+3])
    ulonglong2 db = in1[p4];
    ulonglong2 wl =
        reinterpret_cast<const ulonglong2*>(wlo)[p4 * 32 + lane];
    ulonglong2 wh =
        reinterpret_cast<const ulonglong2*>(whi)[p4 * 32 + lane];
    a00 = ffma2(da.x, wl.x, a00);
    b00 = ffma2(da.y, wl.y, b00);
    a01 = ffma2(da.x, wh.x, a01);
    b01 = ffma2(da.y, wh.y, b01);
    a10 = ffma2(db.x, wl.x, a10);
    b10 = ffma2(db.y, wl.y, b10);
    a11 = ffma2(db.x, wh.x, a11);
    b11 = ffma2(db.y, wh.y, b11);
  }
  o[0][0] = bs[lane] + hsum2(a00) + hsum2(b00);
  o[0][1] = bs[lane + 32] + hsum2(a01) + hsum2(b01);
  o[1][0] = bs[lane] + hsum2(a10) + hsum2(b10);
  o[1][1] = bs[lane + 32] + hsum2(a11) + hsum2(b11);
}

}  // namespace

__global__ void __launch_bounds__(THREADS, 1) fused_pair_kernel(
    const float* __restrict__ Sg, const float* __restrict__ R,
    const float* __restrict__ We0, const float* __restrict__ be0,
    const float* __restrict__ We1, const float* __restrict__ be1,
    const float* __restrict__ We2, const float* __restrict__ be2,
    const float* __restrict__ Wf0, const float* __restrict__ bf0,
    const float* __restrict__ Wf1, const float* __restrict__ bf1,
    const float* __restrict__ Wf2, const float* __restrict__ bf2,
    const float* __restrict__ Wf3, const float* __restrict__ bf3,
    float* __restrict__ out) {
  extern __shared__ char smraw[];
  Smem* s = reinterpret_cast<Smem*>(smraw);
  const int tid = threadIdx.x;

  // ---- block-wide fit-weight staging (f32x2-friendly layout)
  for (int i = tid; i < 64 * 32; i += THREADS) {
    int p4 = i >> 5, j = i & 31;
    s->wf0lo[i] = make_float4(Wf0[(4 * p4 + 0) * 64 + j],
                              Wf0[(4 * p4 + 1) * 64 + j],
                              Wf0[(4 * p4 + 2) * 64 + j],
                              Wf0[(4 * p4 + 3) * 64 + j]);
    s->wf0hi[i] = make_float4(Wf0[(4 * p4 + 0) * 64 + j + 32],
                              Wf0[(4 * p4 + 1) * 64 + j + 32],
                              Wf0[(4 * p4 + 2) * 64 + j + 32],
                              Wf0[(4 * p4 + 3) * 64 + j + 32]);
  }
  for (int i = tid; i < 16 * 32; i += THREADS) {
    int p4 = i >> 5, j = i & 31;
    s->wf1lo[i] = make_float4(Wf1[(4 * p4 + 0) * 64 + j],
                              Wf1[(4 * p4 + 1) * 64 + j],
                              Wf1[(4 * p4 + 2) * 64 + j],
                              Wf1[(4 * p4 + 3) * 64 + j]);
    s->wf1hi[i] = make_float4(Wf1[(4 * p4 + 0) * 64 + j + 32],
                              Wf1[(4 * p4 + 1) * 64 + j + 32],
                              Wf1[(4 * p4 + 2) * 64 + j + 32],
                              Wf1[(4 * p4 + 3) * 64 + j + 32]);
    s->wf2lo[i] = make_float4(Wf2[(4 * p4 + 0) * 64 + j],
                              Wf2[(4 * p4 + 1) * 64 + j],
                              Wf2[(4 * p4 + 2) * 64 + j],
                              Wf2[(4 * p4 + 3) * 64 + j]);
    s->wf2hi[i] = make_float4(Wf2[(4 * p4 + 0) * 64 + j + 32],
                              Wf2[(4 * p4 + 1) * 64 + j + 32],
                              Wf2[(4 * p4 + 2) * 64 + j + 32],
                              Wf2[(4 * p4 + 3) * 64 + j + 32]);
  }
  if (tid < 64) {
    s->bf0s[tid] = bf0[tid];
    s->bf1s[tid] = bf1[tid];
    s->bf2s[tid] = bf2[tid];
    s->wf3s[tid] = Wf3[tid];
  }
  if (tid == 0) s->bf3s = bf3[0];

  const int lane = tid & 31, wid = tid >> 5;

  // ---- per-lane embedding weights as f32x2 register pairs over input index
  ull we0p[2], we1p[16], we2p[16];
  we0p[0] = pack2(We0[0 * 32 + lane], We0[1 * 32 + lane]);
  we0p[1] = pack2(We0[2 * 32 + lane], We0[3 * 32 + lane]);
#pragma unroll
  for (int t = 0; t < 16; t++) {
    we1p[t] = pack2(We1[(2 * t) * 32 + lane], We1[(2 * t + 1) * 32 + lane]);
    we2p[t] = pack2(We2[(2 * t) * 32 + lane], We2[(2 * t + 1) * 32 + lane]);
  }
  const float be0v = be0[lane], be1v = be1[lane], be2v = be2[lane];
  __syncthreads();

  const int ak = lane >> 2, al = lane & 3;  // A[k][l] ownership: lane = k*4+l

  for (int it = blockIdx.x * WARPS + wid; it < NPAIR2; it += GRID * WARPS) {
    const int pair0 = it * 2;  // pair0, pair0+1 share the same b
    if (lane < Mm) {
      const float4* sgp = reinterpret_cast<const float4*>(Sg) + pair0 * Mm;
      const float4* rp = reinterpret_cast<const float4*>(R) + pair0 * Mm;
      s->sg[wid][0][lane] = sgp[lane];
      s->sg[wid][1][lane] = sgp[Mm + lane];
      s->rr[wid][0][lane] = rp[lane];
      s->rr[wid][1][lane] = rp[Mm + lane];
    }
    __syncwarp();

    float bm[2][4] = {{0.f, 0.f, 0.f, 0.f}, {0.f, 0.f, 0.f, 0.f}};
    float aacc[2] = {0.f, 0.f};

#pragma unroll 1
    for (int m = 0; m < Mm; m++) {
      // layer 0 (4 -> 32, sigmoid), both pairs
#pragma unroll
      for (int pp = 0; pp < 2; pp++) {
        ulonglong2 x2 =
            reinterpret_cast<const ulonglong2*>(s->sg[wid][pp])[m];
        ull acc = ffma2(x2.x, we0p[0], 0ULL);
        acc = ffma2(x2.y, we0p[1], acc);
        s->hbuf[wid][pp][0][lane] = sigmoid_fast(be0v + hsum2(acc));
      }
      __syncwarp();
      // layer 1 (32 -> 32, tanh), both pairs
#pragma unroll
      for (int pp = 0; pp < 2; pp++) {
        const ulonglong2* hb =
            reinterpret_cast<const ulonglong2*>(s->hbuf[wid][pp][0]);
        ull acc0 = 0, acc1 = 0;
#pragma unroll
        for (int t = 0; t < 8; t++) {
          ulonglong2 v = hb[t];
          acc0 = ffma2(v.x, we1p[2 * t], acc0);
          acc1 = ffma2(v.y, we1p[2 * t + 1], acc1);
        }
        s->hbuf[wid][pp][1][lane] =
            tanh_fast(be1v + hsum2(acc0) + hsum2(acc1));
      }
      __syncwarp();
      // layer 2 (32 -> 32, linear) + bilinear accumulation, both pairs
#pragma unroll
      for (int pp = 0; pp < 2; pp++) {
        const ulonglong2* hb =
            reinterpret_cast<const ulonglong2*>(s->hbuf[wid][pp][1]);
        ull acc0 = 0, acc1 = 0;
#pragma unroll
        for (int t = 0; t < 8; t++) {
          ulonglong2 v = hb[t];
          acc0 = ffma2(v.x, we2p[2 * t], acc0);
          acc1 = ffma2(v.y, we2p[2 * t + 1], acc1);
        }
        float g = be2v + hsum2(acc0) + hsum2(acc1);  // G[m][lane]
        float4 r = s->rr[wid][pp][m];
        bm[pp][0] += r.x * g;
        bm[pp][1] += r.y * g;
        bm[pp][2] += r.z * g;
        bm[pp][3] += r.w * g;
        float gk = __shfl_sync(FULLM, g, ak);
        float rl = (al == 0) ? r.x : (al == 1) ? r.y : (al == 2) ? r.z : r.w;
        aacc[pp] += gk * rl;
      }
    }

    // ---- D[k][n] = sum_l A[k][l] * Bm[l][n], lane = n (both pairs)
#pragma unroll
    for (int pp = 0; pp < 2; pp++) {
#pragma unroll
      for (int k = 0; k < 8; k++) {
        float d = 0.f;
#pragma unroll
        for (int l = 0; l < 4; l++) {
          float a = __shfl_sync(FULLM, aacc[pp], k * 4 + l);
          d += a * bm[pp][l];
        }
        s->dbuf[wid][pp][k * 32 + lane] = d;
      }
    }
    __syncwarp();

    // ---- fit MLP: 256 -> 64 (tanh) -> 64 (sigmoid) -> 64 (tanh) -> 1
    float o[2][2];
    fit_layer2<256>(s->wf0lo, s->wf0hi, s->bf0s,
                    reinterpret_cast<const ulonglong2*>(s->dbuf[wid][0]),
                    reinterpret_cast<const ulonglong2*>(s->dbuf[wid][1]),
                    lane, o);
    s->ybuf[wid][0][lane] = tanh_fast(o[0][0]);
    s->ybuf[wid][0][lane + 32] = tanh_fast(o[0][1]);
    s->ybuf[wid][1][lane] = tanh_fast(o[1][0]);
    s->ybuf[wid][1][lane + 32] = tanh_fast(o[1][1]);
    __syncwarp();

    fit_layer2<64>(s->wf1lo, s->wf1hi, s->bf1s,
                   reinterpret_cast<const ulonglong2*>(s->ybuf[wid][0]),
                   reinterpret_cast<const ulonglong2*>(s->ybuf[wid][1]),
                   lane, o);
    float y00 = sigmoid_fast(o[0][0]), y01 = sigmoid_fast(o[0][1]);
    float y10 = sigmoid_fast(o[1][0]), y11 = sigmoid_fast(o[1][1]);
    __syncwarp();  // all lanes done reading ybuf before overwrite
    s->ybuf[wid][0][lane] = y00;
    s->ybuf[wid][0][lane + 32] = y01;
    s->ybuf[wid][1][lane] = y10;
    s->ybuf[wid][1][lane + 32] = y11;
    __syncwarp();

    fit_layer2<64>(s->wf2lo, s->wf2hi, s->bf2s,
                   reinterpret_cast<const ulonglong2*>(s->ybuf[wid][0]),
                   reinterpret_cast<const ulonglong2*>(s->ybuf[wid][1]),
                   lane, o);
    __syncwarp();  // all lanes done reading ybuf (loop reuse safety)

    // ---- final 64 -> 1 + warp reduction, accumulate mean into out[b]
    float wl = s->wf3s[lane], wh = s->wf3s[lane + 32];
    float q = tanh_fast(o[0][0]) * wl + tanh_fast(o[0][1]) * wh +
              tanh_fast(o[1][0]) * wl + tanh_fast(o[1][1]) * wh;
#pragma unroll
    for (int off = 16; off; off >>= 1) q += __shfl_xor_sync(FULLM, q, off);
    if (lane == 0) {
      atomicAdd(out + (pair0 >> 9),
                (q + 2.0f * s->bf3s) * (1.0f / (float)Nn));
    }
  }
}

extern "C" void kernel_launch(void* const* d_in, const int* in_sizes, int n_in,
                              void* d_out, int out_size) {
  const float* Sg = (const float*)d_in[0];
  const float* R = (const float*)d_in[1];
  const float* We0 = (const float*)d_in[2];
  const float* be0 = (const float*)d_in[3];
  const float* We1 = (const float*)d_in[4];
  const float* be1 = (const float*)d_in[5];
  const float* We2 = (const float*)d_in[6];
  const float* be2 = (const float*)d_in[7];
  const float* Wf0 = (const float*)d_in[8];
  const float* bf0 = (const float*)d_in[9];
  const float* Wf1 = (const float*)d_in[10];
  const float* bf1 = (const float*)d_in[11];
  const float* Wf2 = (const float*)d_in[12];
  const float* bf2 = (const float*)d_in[13];
  const float* Wf3 = (const float*)d_in[14];
  const float* bf3 = (const float*)d_in[15];
  float* out = (float*)d_out;

  (void)in_sizes;
  (void)n_in;

  cudaFuncSetAttribute(fused_pair_kernel,
                       cudaFuncAttributeMaxDynamicSharedMemorySize,
                       (int)sizeof(Smem));

  cudaMemsetAsync(out, 0, (size_t)out_size * sizeof(float));

  fused_pair_kernel<<<GRID, THREADS, sizeof(Smem)>>>(
      Sg, R, We0, be0, We1, be1, We2, be2, Wf0, bf0, Wf1, bf1, Wf2, bf2, Wf3,
      bf3, out);
}

// round 5
// speedup vs baseline: 1.3343x; 1.0556x over previous
#include <cuda_runtime.h>
#include <cstdint>

namespace {

constexpr int Mm = 30;
constexpr int NPAIR = 64 * 512;       // 32768
constexpr int NPAIR2 = NPAIR / 2;     // 16384 pair-pairs
constexpr int WARPS = 12;
constexpr int THREADS = WARPS * 32;   // 384
constexpr int GRID = 148;
constexpr unsigned FULLM = 0xffffffffu;
constexpr int GSTRIDE = 34;           // G row stride (even -> float2 aligned)

typedef unsigned long long ull;

struct Smem {
  // fit weights packed for f32x2
  float4 wf0lo[64 * 32];
  float4 wf0hi[64 * 32];
  float4 wf1lo[16 * 32];
  float4 wf1hi[16 * 32];
  float4 wf2lo[16 * 32];
  float4 wf2hi[16 * 32];
  // emb mma B-fragment tables, tf32 hi/lo split
  uint2  b1fh[16 * 32];
  uint2  b1fl[16 * 32];
  uint2  b2fh[16 * 32];
  uint2  b2fl[16 * 32];
  float4 w0colf4[32];       // col c: We0[0..3][c]
  float2 bias1f[4 * 32];
  float2 bias2f[4 * 32];
  float  be0s[32];
  float  bf0s[64], bf1s[64], bf2s[64], wf3s[64];
  float  bf3s;
  // per-warp buffers
  float4 sg[WARPS][2][32];      // rows 30,31 zeroed
  float4 rr[WARPS][2][Mm];
  float  gbuf[WARPS][Mm * GSTRIDE];
  float  dbuf[WARPS][2][256];
  float  ybuf[WARPS][2][64];
};

__device__ __forceinline__ float tanh_fast(float x) {
  float y;
  asm("tanh.approx.f32 %0, %1;" : "=f"(y) : "f"(x));
  return y;
}
__device__ __forceinline__ float sigmoid_fast(float x) {
  return 0.5f * tanh_fast(0.5f * x) + 0.5f;
}
__device__ __forceinline__ unsigned f2tf32(float x) {
  unsigned r;
  asm("cvt.rna.tf32.f32 %0, %1;" : "=r"(r) : "f"(x));
  return r;
}
__device__ __forceinline__ void split_tf32(float x, unsigned& hi,
                                           unsigned& lo) {
  hi = f2tf32(x);
  lo = f2tf32(x - __uint_as_float(hi));
}
__device__ __forceinline__ float dot4(float4 a, float4 b) {
  return a.x * b.x + a.y * b.y + a.z * b.z + a.w * b.w;
}
__device__ __forceinline__ void mma8(float c[4], const unsigned a[4], uint2 b) {
  asm volatile(
      "mma.sync.aligned.m16n8k8.row.col.f32.tf32.tf32.f32 "
      "{%0,%1,%2,%3}, {%4,%5,%6,%7}, {%8,%9}, {%0,%1,%2,%3};"
      : "+f"(c[0]), "+f"(c[1]), "+f"(c[2]), "+f"(c[3])
      : "r"(a[0]), "r"(a[1]), "r"(a[2]), "r"(a[3]), "r"(b.x), "r"(b.y));
}
// C-fragment (n-tile u) values regathered into A-fragment (k-tile u) POSITIONS,
// returned as floats (caller splits to tf32 hi/lo).
__device__ __forceinline__ void cvt_c2a_f(const float c[4], float a[4], int e,
                                          int s0, int s1) {
  float x0 = __shfl_sync(FULLM, c[0], s0);
  float x1 = __shfl_sync(FULLM, c[1], s0);
  float x2 = __shfl_sync(FULLM, c[2], s0);
  float x3 = __shfl_sync(FULLM, c[3], s0);
  float y0 = __shfl_sync(FULLM, c[0], s1);
  float y1 = __shfl_sync(FULLM, c[1], s1);
  float y2 = __shfl_sync(FULLM, c[2], s1);
  float y3 = __shfl_sync(FULLM, c[3], s1);
  a[0] = e ? x1 : x0;
  a[1] = e ? x3 : x2;
  a[2] = e ? y1 : y0;
  a[3] = e ? y3 : y2;
}

__device__ __forceinline__ ull pack2(float lo, float hi) {
  ull r;
  asm("mov.b64 %0, {%1, %2};" : "=l"(r) : "f"(lo), "f"(hi));
  return r;
}
__device__ __forceinline__ void unpack2(ull v, float& lo, float& hi) {
  asm("mov.b64 {%0, %1}, %2;" : "=f"(lo), "=f"(hi) : "l"(v));
}
__device__ __forceinline__ ull ffma2(ull a, ull b, ull c) {
  ull d;
  asm("fma.rn.f32x2 %0, %1, %2, %3;" : "=l"(d) : "l"(a), "l"(b), "l"(c));
  return d;
}
__device__ __forceinline__ float hsum2(ull v) {
  float a, b;
  unpack2(v, a, b);
  return a + b;
}

template <int NIN>
__device__ __forceinline__ void fit_layer2(const float4* __restrict__ wlo,
                                           const float4* __restrict__ whi,
                                           const float* __restrict__ bs,
                                           const ulonglong2* __restrict__ in0,
                                           const ulonglong2* __restrict__ in1,
                                           int lane, float o[2][2]) {
  ull a00 = 0, a01 = 0, a10 = 0, a11 = 0;
  ull b00 = 0, b01 = 0, b10 = 0, b11 = 0;
#pragma unroll 8
  for (int p4 = 0; p4 < NIN / 4; p4++) {
    ulonglong2 da = in0[p4];
    ulonglong2 db = in1[p4];
    ulonglong2 wl = reinterpret_cast<const ulonglong2*>(wlo)[p4 * 32 + lane];
    ulonglong2 wh = reinterpret_cast<const ulonglong2*>(whi)[p4 * 32 + lane];
    a00 = ffma2(da.x, wl.x, a00);
    b00 = ffma2(da.y, wl.y, b00);
    a01 = ffma2(da.x, wh.x, a01);
    b01 = ffma2(da.y, wh.y, b01);
    a10 = ffma2(db.x, wl.x, a10);
    b10 = ffma2(db.y, wl.y, b10);
    a11 = ffma2(db.x, wh.x, a11);
    b11 = ffma2(db.y, wh.y, b11);
  }
  o[0][0] = bs[lane] + hsum2(a00) + hsum2(b00);
  o[0][1] = bs[lane + 32] + hsum2(a01) + hsum2(b01);
  o[1][0] = bs[lane] + hsum2(a10) + hsum2(b10);
  o[1][1] = bs[lane + 32] + hsum2(a11) + hsum2(b11);
}

}  // namespace

__global__ void __launch_bounds__(THREADS, 1) fused_pair_kernel(
    const float* __restrict__ Sg, const float* __restrict__ R,
    const float* __restrict__ We0, const float* __restrict__ be0,
    const float* __restrict__ We1, const float* __restrict__ be1,
    const float* __restrict__ We2, const float* __restrict__ be2,
    const float* __restrict__ Wf0, const float* __restrict__ bf0,
    const float* __restrict__ Wf1, const float* __restrict__ bf1,
    const float* __restrict__ Wf2, const float* __restrict__ bf2,
    const float* __restrict__ Wf3, const float* __restrict__ bf3,
    float* __restrict__ out) {
  extern __shared__ char smraw[];
  Smem* s = reinterpret_cast<Smem*>(smraw);
  const int tid = threadIdx.x;

  // ---- fit-weight staging
  for (int i = tid; i < 64 * 32; i += THREADS) {
    int p4 = i >> 5, j = i & 31;
    s->wf0lo[i] =
        make_float4(Wf0[(4 * p4 + 0) * 64 + j], Wf0[(4 * p4 + 1) * 64 + j],
                    Wf0[(4 * p4 + 2) * 64 + j], Wf0[(4 * p4 + 3) * 64 + j]);
    s->wf0hi[i] = make_float4(
        Wf0[(4 * p4 + 0) * 64 + j + 32], Wf0[(4 * p4 + 1) * 64 + j + 32],
        Wf0[(4 * p4 + 2) * 64 + j + 32], Wf0[(4 * p4 + 3) * 64 + j + 32]);
  }
  for (int i = tid; i < 16 * 32; i += THREADS) {
    int p4 = i >> 5, j = i & 31;
    s->wf1lo[i] =
        make_float4(Wf1[(4 * p4 + 0) * 64 + j], Wf1[(4 * p4 + 1) * 64 + j],
                    Wf1[(4 * p4 + 2) * 64 + j], Wf1[(4 * p4 + 3) * 64 + j]);
    s->wf1hi[i] = make_float4(
        Wf1[(4 * p4 + 0) * 64 + j + 32], Wf1[(4 * p4 + 1) * 64 + j + 32],
        Wf1[(4 * p4 + 2) * 64 + j + 32], Wf1[(4 * p4 + 3) * 64 + j + 32]);
    s->wf2lo[i] =
        make_float4(Wf2[(4 * p4 + 0) * 64 + j], Wf2[(4 * p4 + 1) * 64 + j],
                    Wf2[(4 * p4 + 2) * 64 + j], Wf2[(4 * p4 + 3) * 64 + j]);
    s->wf2hi[i] = make_float4(
        Wf2[(4 * p4 + 0) * 64 + j + 32], Wf2[(4 * p4 + 1) * 64 + j + 32],
        Wf2[(4 * p4 + 2) * 64 + j + 32], Wf2[(4 * p4 + 3) * 64 + j + 32]);
  }
  // ---- emb mma B-fragment tables with tf32 hi/lo split
  for (int i = tid; i < 512; i += THREADS) {
    int L = i & 31, ut = i >> 5;
    int u = ut >> 2, t = ut & 3;
    int q = L & 3, g = L >> 2;
    int r0 = u * 8 + q, r1 = r0 + 4, cN = t * 8 + g;
    unsigned h0, l0, h1, l1;
    split_tf32(We1[r0 * 32 + cN], h0, l0);
    split_tf32(We1[r1 * 32 + cN], h1, l1);
    s->b1fh[i] = make_uint2(h0, h1);
    s->b1fl[i] = make_uint2(l0, l1);
    split_tf32(We2[r0 * 32 + cN], h0, l0);
    split_tf32(We2[r1 * 32 + cN], h1, l1);
    s->b2fh[i] = make_uint2(h0, h1);
    s->b2fl[i] = make_uint2(l0, l1);
  }
  for (int i = tid; i < 128; i += THREADS) {
    int t = i >> 5, L = i & 31, q = L & 3;
    s->bias1f[i] = make_float2(be1[t * 8 + 2 * q], be1[t * 8 + 2 * q + 1]);
    s->bias2f[i] = make_float2(be2[t * 8 + 2 * q], be2[t * 8 + 2 * q + 1]);
  }
  if (tid < 32) {
    s->w0colf4[tid] =
        make_float4(We0[tid], We0[32 + tid], We0[64 + tid], We0[96 + tid]);
    s->be0s[tid] = be0[tid];
  }
  if (tid < 64) {
    s->bf0s[tid] = bf0[tid];
    s->bf1s[tid] = bf1[tid];
    s->bf2s[tid] = bf2[tid];
    s->wf3s[tid] = Wf3[tid];
  }
  if (tid == 0) s->bf3s = bf3[0];
  __syncthreads();

  const int lane = tid & 31, wid = tid >> 5;
  const int q = lane & 3, g = lane >> 2;
  const int e = q & 1;
  const int s0 = (lane & ~3) | (q >> 1);
  const int s1 = s0 + 2;
  const int ak = lane >> 2, al = lane & 3;

  for (int it = blockIdx.x * WARPS + wid; it < NPAIR2; it += GRID * WARPS) {
    const int pair0 = it * 2;  // pair0, pair0+1 share the same b
    {
      const float4* sgp = reinterpret_cast<const float4*>(Sg) + pair0 * Mm;
      const float4* rp = reinterpret_cast<const float4*>(R) + pair0 * Mm;
      if (lane < Mm) {
        s->sg[wid][0][lane] = sgp[lane];
        s->sg[wid][1][lane] = sgp[Mm + lane];
        s->rr[wid][0][lane] = rp[lane];
        s->rr[wid][1][lane] = rp[Mm + lane];
      } else {
        s->sg[wid][0][lane] = make_float4(0.f, 0.f, 0.f, 0.f);
        s->sg[wid][1][lane] = make_float4(0.f, 0.f, 0.f, 0.f);
      }
    }
    __syncwarp();

    float bm[2][4] = {{0.f, 0.f, 0.f, 0.f}, {0.f, 0.f, 0.f, 0.f}};
    float aacc[2] = {0.f, 0.f};

#pragma unroll 1
    for (int pp = 0; pp < 2; pp++) {
#pragma unroll 1
      for (int mt = 0; mt < 2; mt++) {
        // ---- layer0 (4->32, sigmoid) built directly in A-fragment layout
        unsigned a1h[4][4], a1l[4][4];
        {
          float4 sgA = s->sg[wid][pp][mt * 16 + g];
          float4 sgB = s->sg[wid][pp][mt * 16 + 8 + g];
#pragma unroll
          for (int u = 0; u < 4; u++) {
            float4 wA = s->w0colf4[u * 8 + q];
            float4 wB = s->w0colf4[u * 8 + q + 4];
            float bA = s->be0s[u * 8 + q];
            float bB = s->be0s[u * 8 + q + 4];
            split_tf32(sigmoid_fast(bA + dot4(sgA, wA)), a1h[u][0], a1l[u][0]);
            split_tf32(sigmoid_fast(bA + dot4(sgB, wA)), a1h[u][1], a1l[u][1]);
            split_tf32(sigmoid_fast(bB + dot4(sgA, wB)), a1h[u][2], a1l[u][2]);
            split_tf32(sigmoid_fast(bB + dot4(sgB, wB)), a1h[u][3], a1l[u][3]);
          }
        }
        // ---- layer1 (32->32) via 3xTF32 mma, bias folded into C init
        float c1[4][4];
#pragma unroll
        for (int nt = 0; nt < 4; nt++) {
          float2 bi = s->bias1f[nt * 32 + lane];
          c1[nt][0] = bi.x;
          c1[nt][1] = bi.y;
          c1[nt][2] = bi.x;
          c1[nt][3] = bi.y;
#pragma unroll
          for (int u = 0; u < 4; u++) {
            uint2 bh = s->b1fh[(u * 4 + nt) * 32 + lane];
            uint2 bl = s->b1fl[(u * 4 + nt) * 32 + lane];
            mma8(c1[nt], a1h[u], bh);
            mma8(c1[nt], a1l[u], bh);
            mma8(c1[nt], a1h[u], bl);
          }
        }
        // ---- tanh + C->A conversion + split
        unsigned a2h[4][4], a2l[4][4];
#pragma unroll
        for (int nt = 0; nt < 4; nt++)
#pragma unroll
          for (int j = 0; j < 4; j++) c1[nt][j] = tanh_fast(c1[nt][j]);
#pragma unroll
        for (int u = 0; u < 4; u++) {
          float af[4];
          cvt_c2a_f(c1[u], af, e, s0, s1);
#pragma unroll
          for (int j = 0; j < 4; j++) split_tf32(af[j], a2h[u][j], a2l[u][j]);
        }
        // ---- layer2 (32->32, linear) via 3xTF32 mma
        float c2[4][4];
#pragma unroll
        for (int nt = 0; nt < 4; nt++) {
          float2 bi = s->bias2f[nt * 32 + lane];
          c2[nt][0] = bi.x;
          c2[nt][1] = bi.y;
          c2[nt][2] = bi.x;
          c2[nt][3] = bi.y;
#pragma unroll
          for (int u = 0; u < 4; u++) {
            uint2 bh = s->b2fh[(u * 4 + nt) * 32 + lane];
            uint2 bl = s->b2fl[(u * 4 + nt) * 32 + lane];
            mma8(c2[nt], a2h[u], bh);
            mma8(c2[nt], a2l[u], bh);
            mma8(c2[nt], a2h[u], bl);
          }
        }
        // ---- store G rows of this m-tile to smem
#pragma unroll
        for (int nt = 0; nt < 4; nt++) {
          int colb = nt * 8 + 2 * q;
          int r0r = mt * 16 + g;
          *reinterpret_cast<float2*>(&s->gbuf[wid][r0r * GSTRIDE + colb]) =
              make_float2(c2[nt][0], c2[nt][1]);
          int r1r = r0r + 8;
          if (r1r < Mm)
            *reinterpret_cast<float2*>(&s->gbuf[wid][r1r * GSTRIDE + colb]) =
                make_float2(c2[nt][2], c2[nt][3]);
        }
      }
      __syncwarp();
      // ---- bilinear accumulation for this pair
#pragma unroll 6
      for (int m = 0; m < Mm; m++) {
        float gv = s->gbuf[wid][m * GSTRIDE + lane];
        float4 r = s->rr[wid][pp][m];
        bm[pp][0] += r.x * gv;
        bm[pp][1] += r.y * gv;
        bm[pp][2] += r.z * gv;
        bm[pp][3] += r.w * gv;
        float gk = __shfl_sync(FULLM, gv, ak);
        float rl = (al == 0) ? r.x : (al == 1) ? r.y : (al == 2) ? r.z : r.w;
        aacc[pp] += gk * rl;
      }
      __syncwarp();  // gbuf reused by next pair
    }

    // ---- D[k][n] = sum_l A[k][l] * Bm[l][n], lane = n (both pairs)
#pragma unroll
    for (int pp = 0; pp < 2; pp++) {
#pragma unroll
      for (int k = 0; k < 8; k++) {
        float d = 0.f;
#pragma unroll
        for (int l = 0; l < 4; l++) {
          float a = __shfl_sync(FULLM, aacc[pp], k * 4 + l);
          d += a * bm[pp][l];
        }
        s->dbuf[wid][pp][k * 32 + lane] = d;
      }
    }
    __syncwarp();

    // ---- fit MLP: 256 -> 64 (tanh) -> 64 (sigmoid) -> 64 (tanh) -> 1
    float o[2][2];
    fit_layer2<256>(s->wf0lo, s->wf0hi, s->bf0s,
                    reinterpret_cast<const ulonglong2*>(s->dbuf[wid][0]),
                    reinterpret_cast<const ulonglong2*>(s->dbuf[wid][1]), lane,
                    o);
    s->ybuf[wid][0][lane] = tanh_fast(o[0][0]);
    s->ybuf[wid][0][lane + 32] = tanh_fast(o[0][1]);
    s->ybuf[wid][1][lane] = tanh_fast(o[1][0]);
    s->ybuf[wid][1][lane + 32] = tanh_fast(o[1][1]);
    __syncwarp();

    fit_layer2<64>(s->wf1lo, s->wf1hi, s->bf1s,
                   reinterpret_cast<const ulonglong2*>(s->ybuf[wid][0]),
                   reinterpret_cast<const ulonglong2*>(s->ybuf[wid][1]), lane,
                   o);
    float y00 = sigmoid_fast(o[0][0]), y01 = sigmoid_fast(o[0][1]);
    float y10 = sigmoid_fast(o[1][0]), y11 = sigmoid_fast(o[1][1]);
    __syncwarp();
    s->ybuf[wid][0][lane] = y00;
    s->ybuf[wid][0][lane + 32] = y01;
    s->ybuf[wid][1][lane] = y10;
    s->ybuf[wid][1][lane + 32] = y11;
    __syncwarp();

    fit_layer2<64>(s->wf2lo, s->wf2hi, s->bf2s,
                   reinterpret_cast<const ulonglong2*>(s->ybuf[wid][0]),
                   reinterpret_cast<const ulonglong2*>(s->ybuf[wid][1]), lane,
                   o);
    __syncwarp();

    // ---- final 64 -> 1 + warp reduction, accumulate mean into out[b]
    float wl = s->wf3s[lane], wh = s->wf3s[lane + 32];
    float qv = tanh_fast(o[0][0]) * wl + tanh_fast(o[0][1]) * wh +
               tanh_fast(o[1][0]) * wl + tanh_fast(o[1][1]) * wh;
#pragma unroll
    for (int off = 16; off; off >>= 1) qv += __shfl_xor_sync(FULLM, qv, off);
    if (lane == 0) {
      atomicAdd(out + (pair0 >> 9), (qv + 2.0f * s->bf3s) * (1.0f / 512.0f));
    }
  }
}

extern "C" void kernel_launch(void* const* d_in, const int* in_sizes, int n_in,
                              void* d_out, int out_size) {
  const float* Sg = (const float*)d_in[0];
  const float* R = (const float*)d_in[1];
  const float* We0 = (const float*)d_in[2];
  const float* be0 = (const float*)d_in[3];
  const float* We1 = (const float*)d_in[4];
  const float* be1 = (const float*)d_in[5];
  const float* We2 = (const float*)d_in[6];
  const float* be2 = (const float*)d_in[7];
  const float* Wf0 = (const float*)d_in[8];
  const float* bf0 = (const float*)d_in[9];
  const float* Wf1 = (const float*)d_in[10];
  const float* bf1 = (const float*)d_in[11];
  const float* Wf2 = (const float*)d_in[12];
  const float* bf2 = (const float*)d_in[13];
  const float* Wf3 = (const float*)d_in[14];
  const float* bf3 = (const float*)d_in[15];
  float* out = (float*)d_out;

  (void)in_sizes;
  (void)n_in;

  cudaFuncSetAttribute(fused_pair_kernel,
                       cudaFuncAttributeMaxDynamicSharedMemorySize,
                       (int)sizeof(Smem));

  cudaMemsetAsync(out, 0, (size_t)out_size * sizeof(float));

  fused_pair_kernel<<<GRID, THREADS, sizeof(Smem)>>>(
      Sg, R, We0, be0, We1, be1, We2, be2, Wf0, bf0, Wf1, bf1, Wf2, bf2, Wf3,
      bf3, out);
}

// round 6
// speedup vs baseline: 1.6739x; 1.2546x over previous
#include <cuda_runtime.h>
#include <cstdint>

namespace {

constexpr int Mm = 30;
constexpr int NPAIR = 64 * 512;       // 32768
constexpr int NPAIR2 = NPAIR / 2;     // 16384 pair-pairs
constexpr int WARPS = 16;
constexpr int THREADS = WARPS * 32;   // 512
constexpr int GRID = 148;
constexpr unsigned FULLM = 0xffffffffu;
constexpr int GSTRIDE = 34;           // G row stride (even -> float2 aligned)

typedef unsigned long long ull;

struct Smem {
  // fit weights packed for f32x2
  float4 wf0lo[64 * 32];
  float4 wf0hi[64 * 32];
  float4 wf1lo[16 * 32];
  float4 wf1hi[16 * 32];
  float4 wf2lo[16 * 32];
  float4 wf2hi[16 * 32];
  // emb mma B-fragment tables: (h0, h1, l0, l1) per lane
  uint4  b1f[16 * 32];
  uint4  b2f[16 * 32];
  float4 w0colf4[32];       // col c: We0[0..3][c]
  float2 bias1f[4 * 32];
  float2 bias2f[4 * 32];
  float  be0s[32];
  float  bf0s[64], bf1s[64], bf2s[64], wf3s[64];
  float  bf3s;
  // per-warp union buffer:
  //   phase 1: gbuf[m*GSTRIDE+col], m<30 (1020 floats)
  //   phase 2: dbuf = [0,512), ybuf = [512,640)
  __align__(16) float ubuf[WARPS][1024];
};

__device__ __forceinline__ float tanh_fast(float x) {
  float y;
  asm("tanh.approx.f32 %0, %1;" : "=f"(y) : "f"(x));
  return y;
}
__device__ __forceinline__ float sigmoid_fast(float x) {
  return 0.5f * tanh_fast(0.5f * x) + 0.5f;
}
__device__ __forceinline__ unsigned f2tf32(float x) {
  unsigned r;
  asm("cvt.rna.tf32.f32 %0, %1;" : "=r"(r) : "f"(x));
  return r;
}
__device__ __forceinline__ void split_tf32(float x, unsigned& hi,
                                           unsigned& lo) {
  hi = f2tf32(x);
  lo = f2tf32(x - __uint_as_float(hi));
}
__device__ __forceinline__ float dot4(float4 a, float4 b) {
  return a.x * b.x + a.y * b.y + a.z * b.z + a.w * b.w;
}
__device__ __forceinline__ void mma8(float c[4], const unsigned a[4],
                                     unsigned bx, unsigned by) {
  asm volatile(
      "mma.sync.aligned.m16n8k8.row.col.f32.tf32.tf32.f32 "
      "{%0,%1,%2,%3}, {%4,%5,%6,%7}, {%8,%9}, {%0,%1,%2,%3};"
      : "+f"(c[0]), "+f"(c[1]), "+f"(c[2]), "+f"(c[3])
      : "r"(a[0]), "r"(a[1]), "r"(a[2]), "r"(a[3]), "r"(bx), "r"(by));
}
// C-fragment (n-tile u) values regathered into A-fragment (k-tile u) positions.
__device__ __forceinline__ void cvt_c2a_f(const float c[4], float a[4], int e,
                                          int s0, int s1) {
  float x0 = __shfl_sync(FULLM, c[0], s0);
  float x1 = __shfl_sync(FULLM, c[1], s0);
  float x2 = __shfl_sync(FULLM, c[2], s0);
  float x3 = __shfl_sync(FULLM, c[3], s0);
  float y0 = __shfl_sync(FULLM, c[0], s1);
  float y1 = __shfl_sync(FULLM, c[1], s1);
  float y2 = __shfl_sync(FULLM, c[2], s1);
  float y3 = __shfl_sync(FULLM, c[3], s1);
  a[0] = e ? x1 : x0;
  a[1] = e ? x3 : x2;
  a[2] = e ? y1 : y0;
  a[3] = e ? y3 : y2;
}

__device__ __forceinline__ void unpack2(ull v, float& lo, float& hi) {
  asm("mov.b64 {%0, %1}, %2;" : "=f"(lo), "=f"(hi) : "l"(v));
}
__device__ __forceinline__ ull ffma2(ull a, ull b, ull c) {
  ull d;
  asm("fma.rn.f32x2 %0, %1, %2, %3;" : "=l"(d) : "l"(a), "l"(b), "l"(c));
  return d;
}
__device__ __forceinline__ float hsum2(ull v) {
  float a, b;
  unpack2(v, a, b);
  return a + b;
}

template <int NIN>
__device__ __forceinline__ void fit_layer2(const float4* __restrict__ wlo,
                                           const float4* __restrict__ whi,
                                           const float* __restrict__ bs,
                                           const ulonglong2* __restrict__ in0,
                                           const ulonglong2* __restrict__ in1,
                                           int lane, float o[2][2]) {
  ull a00 = 0, a01 = 0, a10 = 0, a11 = 0;
  ull b00 = 0, b01 = 0, b10 = 0, b11 = 0;
#pragma unroll 8
  for (int p4 = 0; p4 < NIN / 4; p4++) {
    ulonglong2 da = in0[p4];
    ulonglong2 db = in1[p4];
    ulonglong2 wl = reinterpret_cast<const ulonglong2*>(wlo)[p4 * 32 + lane];
    ulonglong2 wh = reinterpret_cast<const ulonglong2*>(whi)[p4 * 32 + lane];
    a00 = ffma2(da.x, wl.x, a00);
    b00 = ffma2(da.y, wl.y, b00);
    a01 = ffma2(da.x, wh.x, a01);
    b01 = ffma2(da.y, wh.y, b01);
    a10 = ffma2(db.x, wl.x, a10);
    b10 = ffma2(db.y, wl.y, b10);
    a11 = ffma2(db.x, wh.x, a11);
    b11 = ffma2(db.y, wh.y, b11);
  }
  o[0][0] = bs[lane] + hsum2(a00) + hsum2(b00);
  o[0][1] = bs[lane + 32] + hsum2(a01) + hsum2(b01);
  o[1][0] = bs[lane] + hsum2(a10) + hsum2(b10);
  o[1][1] = bs[lane + 32] + hsum2(a11) + hsum2(b11);
}

}  // namespace

__global__ void __launch_bounds__(THREADS, 1) fused_pair_kernel(
    const float* __restrict__ Sg, const float* __restrict__ R,
    const float* __restrict__ We0, const float* __restrict__ be0,
    const float* __restrict__ We1, const float* __restrict__ be1,
    const float* __restrict__ We2, const float* __restrict__ be2,
    const float* __restrict__ Wf0, const float* __restrict__ bf0,
    const float* __restrict__ Wf1, const float* __restrict__ bf1,
    const float* __restrict__ Wf2, const float* __restrict__ bf2,
    const float* __restrict__ Wf3, const float* __restrict__ bf3,
    float* __restrict__ out) {
  extern __shared__ char smraw[];
  Smem* s = reinterpret_cast<Smem*>(smraw);
  const int tid = threadIdx.x;

  // ---- fit-weight staging
  for (int i = tid; i < 64 * 32; i += THREADS) {
    int p4 = i >> 5, j = i & 31;
    s->wf0lo[i] =
        make_float4(Wf0[(4 * p4 + 0) * 64 + j], Wf0[(4 * p4 + 1) * 64 + j],
                    Wf0[(4 * p4 + 2) * 64 + j], Wf0[(4 * p4 + 3) * 64 + j]);
    s->wf0hi[i] = make_float4(
        Wf0[(4 * p4 + 0) * 64 + j + 32], Wf0[(4 * p4 + 1) * 64 + j + 32],
        Wf0[(4 * p4 + 2) * 64 + j + 32], Wf0[(4 * p4 + 3) * 64 + j + 32]);
  }
  for (int i = tid; i < 16 * 32; i += THREADS) {
    int p4 = i >> 5, j = i & 31;
    s->wf1lo[i] =
        make_float4(Wf1[(4 * p4 + 0) * 64 + j], Wf1[(4 * p4 + 1) * 64 + j],
                    Wf1[(4 * p4 + 2) * 64 + j], Wf1[(4 * p4 + 3) * 64 + j]);
    s->wf1hi[i] = make_float4(
        Wf1[(4 * p4 + 0) * 64 + j + 32], Wf1[(4 * p4 + 1) * 64 + j + 32],
        Wf1[(4 * p4 + 2) * 64 + j + 32], Wf1[(4 * p4 + 3) * 64 + j + 32]);
    s->wf2lo[i] =
        make_float4(Wf2[(4 * p4 + 0) * 64 + j], Wf2[(4 * p4 + 1) * 64 + j],
                    Wf2[(4 * p4 + 2) * 64 + j], Wf2[(4 * p4 + 3) * 64 + j]);
    s->wf2hi[i] = make_float4(
        Wf2[(4 * p4 + 0) * 64 + j + 32], Wf2[(4 * p4 + 1) * 64 + j + 32],
        Wf2[(4 * p4 + 2) * 64 + j + 32], Wf2[(4 * p4 + 3) * 64 + j + 32]);
  }
  // ---- emb mma B-fragment tables, (hi0,hi1,lo0,lo1) fused
  for (int i = tid; i < 512; i += THREADS) {
    int L = i & 31, ut = i >> 5;
    int u = ut >> 2, t = ut & 3;
    int q = L & 3, g = L >> 2;
    int r0 = u * 8 + q, r1 = r0 + 4, cN = t * 8 + g;
    unsigned h0, l0, h1, l1;
    split_tf32(We1[r0 * 32 + cN], h0, l0);
    split_tf32(We1[r1 * 32 + cN], h1, l1);
    s->b1f[i] = make_uint4(h0, h1, l0, l1);
    split_tf32(We2[r0 * 32 + cN], h0, l0);
    split_tf32(We2[r1 * 32 + cN], h1, l1);
    s->b2f[i] = make_uint4(h0, h1, l0, l1);
  }
  for (int i = tid; i < 128; i += THREADS) {
    int t = i >> 5, L = i & 31, q = L & 3;
    s->bias1f[i] = make_float2(be1[t * 8 + 2 * q], be1[t * 8 + 2 * q + 1]);
    s->bias2f[i] = make_float2(be2[t * 8 + 2 * q], be2[t * 8 + 2 * q + 1]);
  }
  if (tid < 32) {
    s->w0colf4[tid] =
        make_float4(We0[tid], We0[32 + tid], We0[64 + tid], We0[96 + tid]);
    s->be0s[tid] = be0[tid];
  }
  if (tid < 64) {
    s->bf0s[tid] = bf0[tid];
    s->bf1s[tid] = bf1[tid];
    s->bf2s[tid] = bf2[tid];
    s->wf3s[tid] = Wf3[tid];
  }
  if (tid == 0) s->bf3s = bf3[0];
  __syncthreads();

  const int lane = tid & 31, wid = tid >> 5;
  const int q = lane & 3, g = lane >> 2;
  const int e = q & 1;
  const int s0 = (lane & ~3) | (q >> 1);
  const int s1 = s0 + 2;

  float* const gbuf = s->ubuf[wid];           // phase-1 view
  float* const dbuf = s->ubuf[wid];           // phase-2: [0,512)
  float* const ybuf = s->ubuf[wid] + 512;     // phase-2: [512,640)

  const float4* const Sg4 = reinterpret_cast<const float4*>(Sg);
  const float4* const R4 = reinterpret_cast<const float4*>(R);

  for (int it = blockIdx.x * WARPS + wid; it < NPAIR2; it += GRID * WARPS) {
    const int pair0 = it * 2;  // pair0, pair0+1 share the same b

    float bm[2][4] = {{0.f, 0.f, 0.f, 0.f}, {0.f, 0.f, 0.f, 0.f}};

#pragma unroll 1
    for (int pp = 0; pp < 2; pp++) {
      const float4* const sgb = Sg4 + (pair0 + pp) * Mm;
#pragma unroll 1
      for (int mt = 0; mt < 2; mt++) {
        // ---- layer0 (4->32, sigmoid) built directly in A-fragment layout
        unsigned a1h[4][4], a1l[4][4];
        {
          int rA = mt * 16 + g;        // <= 23, always valid
          int rB = rA + 8;             // up to 31
          float4 sgA = sgb[rA];
          float4 sgB = (rB < Mm) ? sgb[rB] : make_float4(0.f, 0.f, 0.f, 0.f);
#pragma unroll
          for (int u = 0; u < 4; u++) {
            float4 wA = s->w0colf4[u * 8 + q];
            float4 wB = s->w0colf4[u * 8 + q + 4];
            float bA = s->be0s[u * 8 + q];
            float bB = s->be0s[u * 8 + q + 4];
            split_tf32(sigmoid_fast(bA + dot4(sgA, wA)), a1h[u][0], a1l[u][0]);
            split_tf32(sigmoid_fast(bA + dot4(sgB, wA)), a1h[u][1], a1l[u][1]);
            split_tf32(sigmoid_fast(bB + dot4(sgA, wB)), a1h[u][2], a1l[u][2]);
            split_tf32(sigmoid_fast(bB + dot4(sgB, wB)), a1h[u][3], a1l[u][3]);
          }
        }
        // ---- layer1 (32->32) via 3xTF32 mma, bias folded into C init
        float c1[4][4];
#pragma unroll
        for (int nt = 0; nt < 4; nt++) {
          float2 bi = s->bias1f[nt * 32 + lane];
          c1[nt][0] = bi.x;
          c1[nt][1] = bi.y;
          c1[nt][2] = bi.x;
          c1[nt][3] = bi.y;
#pragma unroll
          for (int u = 0; u < 4; u++) {
            uint4 bf = s->b1f[(u * 4 + nt) * 32 + lane];
            mma8(c1[nt], a1h[u], bf.x, bf.y);
            mma8(c1[nt], a1l[u], bf.x, bf.y);
            mma8(c1[nt], a1h[u], bf.z, bf.w);
          }
        }
        // ---- tanh + C->A conversion + split
        unsigned a2h[4][4], a2l[4][4];
#pragma unroll
        for (int nt = 0; nt < 4; nt++)
#pragma unroll
          for (int j = 0; j < 4; j++) c1[nt][j] = tanh_fast(c1[nt][j]);
#pragma unroll
        for (int u = 0; u < 4; u++) {
          float af[4];
          cvt_c2a_f(c1[u], af, e, s0, s1);
#pragma unroll
          for (int j = 0; j < 4; j++) split_tf32(af[j], a2h[u][j], a2l[u][j]);
        }
        // ---- layer2 (32->32, linear) via 3xTF32 mma
        float c2[4][4];
#pragma unroll
        for (int nt = 0; nt < 4; nt++) {
          float2 bi = s->bias2f[nt * 32 + lane];
          c2[nt][0] = bi.x;
          c2[nt][1] = bi.y;
          c2[nt][2] = bi.x;
          c2[nt][3] = bi.y;
#pragma unroll
          for (int u = 0; u < 4; u++) {
            uint4 bf = s->b2f[(u * 4 + nt) * 32 + lane];
            mma8(c2[nt], a2h[u], bf.x, bf.y);
            mma8(c2[nt], a2l[u], bf.x, bf.y);
            mma8(c2[nt], a2h[u], bf.z, bf.w);
          }
        }
        // ---- store G rows of this m-tile
#pragma unroll
        for (int nt = 0; nt < 4; nt++) {
          int colb = nt * 8 + 2 * q;
          int r0r = mt * 16 + g;
          *reinterpret_cast<float2*>(&gbuf[r0r * GSTRIDE + colb]) =
              make_float2(c2[nt][0], c2[nt][1]);
          int r1r = r0r + 8;
          if (r1r < Mm)
            *reinterpret_cast<float2*>(&gbuf[r1r * GSTRIDE + colb]) =
                make_float2(c2[nt][2], c2[nt][3]);
        }
      }
      __syncwarp();
      // ---- bilinear: Bm[l][lane] += R[m][l] * G[m][lane]
      const float4* const rb = R4 + (pair0 + pp) * Mm;
#pragma unroll 6
      for (int m = 0; m < Mm; m++) {
        float gv = gbuf[m * GSTRIDE + lane];
        float4 r = rb[m];
        bm[pp][0] += r.x * gv;
        bm[pp][1] += r.y * gv;
        bm[pp][2] += r.z * gv;
        bm[pp][3] += r.w * gv;
      }
      __syncwarp();  // gbuf reused (next pp emb / D store)
    }

    // ---- D[k][n] = sum_l A[k][l]*Bm[l][n] with A = Bm^T:
    //      D[k][n] = sum_l Bm[l][k] * Bm[l][n], lane = n
#pragma unroll
    for (int pp = 0; pp < 2; pp++) {
#pragma unroll
      for (int k = 0; k < 8; k++) {
        float d = 0.f;
#pragma unroll
        for (int l = 0; l < 4; l++) {
          float a = __shfl_sync(FULLM, bm[pp][l], k);  // Bm[l][k]
          d += a * bm[pp][l];
        }
        dbuf[pp * 256 + k * 32 + lane] = d;
      }
    }
    __syncwarp();

    // ---- fit MLP: 256 -> 64 (tanh) -> 64 (sigmoid) -> 64 (tanh) -> 1
    float o[2][2];
    fit_layer2<256>(s->wf0lo, s->wf0hi, s->bf0s,
                    reinterpret_cast<const ulonglong2*>(dbuf),
                    reinterpret_cast<const ulonglong2*>(dbuf + 256), lane, o);
    ybuf[lane] = tanh_fast(o[0][0]);
    ybuf[lane + 32] = tanh_fast(o[0][1]);
    ybuf[64 + lane] = tanh_fast(o[1][0]);
    ybuf[64 + lane + 32] = tanh_fast(o[1][1]);
    __syncwarp();

    fit_layer2<64>(s->wf1lo, s->wf1hi, s->bf1s,
                   reinterpret_cast<const ulonglong2*>(ybuf),
                   reinterpret_cast<const ulonglong2*>(ybuf + 64), lane, o);
    float y00 = sigmoid_fast(o[0][0]), y01 = sigmoid_fast(o[0][1]);
    float y10 = sigmoid_fast(o[1][0]), y11 = sigmoid_fast(o[1][1]);
    __syncwarp();
    ybuf[lane] = y00;
    ybuf[lane + 32] = y01;
    ybuf[64 + lane] = y10;
    ybuf[64 + lane + 32] = y11;
    __syncwarp();

    fit_layer2<64>(s->wf2lo, s->wf2hi, s->bf2s,
                   reinterpret_cast<const ulonglong2*>(ybuf),
                   reinterpret_cast<const ulonglong2*>(ybuf + 64), lane, o);
    __syncwarp();

    // ---- final 64 -> 1 + warp reduction, accumulate mean into out[b]
    float wl = s->wf3s[lane], wh = s->wf3s[lane + 32];
    float qv = tanh_fast(o[0][0]) * wl + tanh_fast(o[0][1]) * wh +
               tanh_fast(o[1][0]) * wl + tanh_fast(o[1][1]) * wh;
#pragma unroll
    for (int off = 16; off; off >>= 1) qv += __shfl_xor_sync(FULLM, qv, off);
    if (lane == 0) {
      atomicAdd(out + (pair0 >> 9), (qv + 2.0f * s->bf3s) * (1.0f / 512.0f));
    }
  }
}

extern "C" void kernel_launch(void* const* d_in, const int* in_sizes, int n_in,
                              void* d_out, int out_size) {
  const float* Sg = (const float*)d_in[0];
  const float* R = (const float*)d_in[1];
  const float* We0 = (const float*)d_in[2];
  const float* be0 = (const float*)d_in[3];
  const float* We1 = (const float*)d_in[4];
  const float* be1 = (const float*)d_in[5];
  const float* We2 = (const float*)d_in[6];
  const float* be2 = (const float*)d_in[7];
  const float* Wf0 = (const float*)d_in[8];
  const float* bf0 = (const float*)d_in[9];
  const float* Wf1 = (const float*)d_in[10];
  const float* bf1 = (const float*)d_in[11];
  const float* Wf2 = (const float*)d_in[12];
  const float* bf2 = (const float*)d_in[13];
  const float* Wf3 = (const float*)d_in[14];
  const float* bf3 = (const float*)d_in[15];
  float* out = (float*)d_out;

  (void)in_sizes;
  (void)n_in;

  cudaFuncSetAttribute(fused_pair_kernel,
                       cudaFuncAttributeMaxDynamicSharedMemorySize,
                       (int)sizeof(Smem));

  cudaMemsetAsync(out, 0, (size_t)out_size * sizeof(float));

  fused_pair_kernel<<<GRID, THREADS, sizeof(Smem)>>>(
      Sg, R, We0, be0, We1, be1, We2, be2, Wf0, bf0, Wf1, bf1, Wf2, bf2, Wf3,
      bf3, out);
}

// round 7
// speedup vs baseline: 1.8475x; 1.1037x over previous
#include <cuda_runtime.h>
#include <cstdint>

namespace {

constexpr int Mm = 30;
constexpr int NPAIR = 64 * 512;       // 32768
constexpr int NPAIR2 = NPAIR / 2;     // 16384 pair-pairs
constexpr unsigned FULLM = 0xffffffffu;
constexpr int GSTRIDE = 34;

// emb kernel config
constexpr int WARPS1 = 12;
constexpr int THREADS1 = WARPS1 * 32;  // 384
constexpr int GRID1 = 296;             // 2 blocks/SM

// fit kernel config
constexpr int WARPS2 = 16;
constexpr int THREADS2 = WARPS2 * 32;  // 512
constexpr int GRID2 = 148;
constexpr int NTILES = NPAIR / 16;     // 2048 (16 pairs per tile)

struct Smem1 {
  uint4  b1f[16 * 32];      // emb layer1 B-fragments (h0,h1,l0,l1)
  uint4  b2f[16 * 32];
  float4 w0colf4[32];
  float2 bias1f[4 * 32];
  float2 bias2f[4 * 32];
  float  be0s[32];
  __align__(16) float gbuf[WARPS1][1024];
};

struct Smem2 {
  uint4  f0[32 * 8 * 32];   // fit0 B-frags [(kt*8+nt)*32+lane]  128 KB
  uint4  f1[8 * 8 * 32];    // 32 KB
  uint4  f2[8 * 8 * 32];    // 32 KB
  float2 bias0f[8 * 32];
  float2 bias1f[8 * 32];
  float2 bias2f[8 * 32];
  float  wf3s[64];
  float  bf3s;
};

__device__ float Dg[NPAIR * 256];  // 32 MB scratch: D matrix

__device__ __forceinline__ float tanh_fast(float x) {
  float y;
  asm("tanh.approx.f32 %0, %1;" : "=f"(y) : "f"(x));
  return y;
}
__device__ __forceinline__ float sigmoid_fast(float x) {
  return 0.5f * tanh_fast(0.5f * x) + 0.5f;
}
__device__ __forceinline__ unsigned f2tf32(float x) {
  unsigned r;
  asm("cvt.rna.tf32.f32 %0, %1;" : "=r"(r) : "f"(x));
  return r;
}
__device__ __forceinline__ void split_tf32(float x, unsigned& hi,
                                           unsigned& lo) {
  hi = f2tf32(x);
  lo = f2tf32(x - __uint_as_float(hi));
}
__device__ __forceinline__ float dot4(float4 a, float4 b) {
  return a.x * b.x + a.y * b.y + a.z * b.z + a.w * b.w;
}
__device__ __forceinline__ void mma8(float c[4], const unsigned a[4],
                                     unsigned bx, unsigned by) {
  asm volatile(
      "mma.sync.aligned.m16n8k8.row.col.f32.tf32.tf32.f32 "
      "{%0,%1,%2,%3}, {%4,%5,%6,%7}, {%8,%9}, {%0,%1,%2,%3};"
      : "+f"(c[0]), "+f"(c[1]), "+f"(c[2]), "+f"(c[3])
      : "r"(a[0]), "r"(a[1]), "r"(a[2]), "r"(a[3]), "r"(bx), "r"(by));
}
// C-fragment of n-tile u -> A-fragment of k-tile u (proven in R5/R6).
__device__ __forceinline__ void cvt_c2a_f(const float c[4], float a[4], int e,
                                          int s0, int s1) {
  float x0 = __shfl_sync(FULLM, c[0], s0);
  float x1 = __shfl_sync(FULLM, c[1], s0);
  float x2 = __shfl_sync(FULLM, c[2], s0);
  float x3 = __shfl_sync(FULLM, c[3], s0);
  float y0 = __shfl_sync(FULLM, c[0], s1);
  float y1 = __shfl_sync(FULLM, c[1], s1);
  float y2 = __shfl_sync(FULLM, c[2], s1);
  float y3 = __shfl_sync(FULLM, c[3], s1);
  a[0] = e ? x1 : x0;
  a[1] = e ? x3 : x2;
  a[2] = e ? y1 : y0;
  a[3] = e ? y3 : y2;
}

}  // namespace

// ======================= Kernel 1: emb MLP + bilinear -> D =================

__global__ void __launch_bounds__(THREADS1, 2) emb_kernel(
    const float* __restrict__ Sg, const float* __restrict__ R,
    const float* __restrict__ We0, const float* __restrict__ be0,
    const float* __restrict__ We1, const float* __restrict__ be1,
    const float* __restrict__ We2, const float* __restrict__ be2) {
  extern __shared__ char smraw[];
  Smem1* s = reinterpret_cast<Smem1*>(smraw);
  const int tid = threadIdx.x;

  for (int i = tid; i < 512; i += THREADS1) {
    int L = i & 31, ut = i >> 5;
    int u = ut >> 2, t = ut & 3;
    int q = L & 3, g = L >> 2;
    int r0 = u * 8 + q, r1 = r0 + 4, cN = t * 8 + g;
    unsigned h0, l0, h1, l1;
    split_tf32(We1[r0 * 32 + cN], h0, l0);
    split_tf32(We1[r1 * 32 + cN], h1, l1);
    s->b1f[i] = make_uint4(h0, h1, l0, l1);
    split_tf32(We2[r0 * 32 + cN], h0, l0);
    split_tf32(We2[r1 * 32 + cN], h1, l1);
    s->b2f[i] = make_uint4(h0, h1, l0, l1);
  }
  for (int i = tid; i < 128; i += THREADS1) {
    int t = i >> 5, L = i & 31, q = L & 3;
    s->bias1f[i] = make_float2(be1[t * 8 + 2 * q], be1[t * 8 + 2 * q + 1]);
    s->bias2f[i] = make_float2(be2[t * 8 + 2 * q], be2[t * 8 + 2 * q + 1]);
  }
  if (tid < 32) {
    s->w0colf4[tid] =
        make_float4(We0[tid], We0[32 + tid], We0[64 + tid], We0[96 + tid]);
    s->be0s[tid] = be0[tid];
  }
  __syncthreads();

  const int lane = tid & 31, wid = tid >> 5;
  const int q = lane & 3, g = lane >> 2;
  const int e = q & 1;
  const int s0 = (lane & ~3) | (q >> 1);
  const int s1 = s0 + 2;

  float* const gbuf = s->gbuf[wid];
  const float4* const Sg4 = reinterpret_cast<const float4*>(Sg);
  const float4* const R4 = reinterpret_cast<const float4*>(R);

  for (int it = blockIdx.x * WARPS1 + wid; it < NPAIR2; it += GRID1 * WARPS1) {
    const int pair0 = it * 2;
    float bm[2][4] = {{0.f, 0.f, 0.f, 0.f}, {0.f, 0.f, 0.f, 0.f}};

#pragma unroll 1
    for (int pp = 0; pp < 2; pp++) {
      const float4* const sgb = Sg4 + (pair0 + pp) * Mm;
#pragma unroll 1
      for (int mt = 0; mt < 2; mt++) {
        // layer0 (4->32, sigmoid) in A-fragment layout
        unsigned a1h[4][4], a1l[4][4];
        {
          int rA = mt * 16 + g;
          int rB = rA + 8;
          float4 sgA = sgb[rA];
          float4 sgB = (rB < Mm) ? sgb[rB] : make_float4(0.f, 0.f, 0.f, 0.f);
#pragma unroll
          for (int u = 0; u < 4; u++) {
            float4 wA = s->w0colf4[u * 8 + q];
            float4 wB = s->w0colf4[u * 8 + q + 4];
            float bA = s->be0s[u * 8 + q];
            float bB = s->be0s[u * 8 + q + 4];
            split_tf32(sigmoid_fast(bA + dot4(sgA, wA)), a1h[u][0], a1l[u][0]);
            split_tf32(sigmoid_fast(bA + dot4(sgB, wA)), a1h[u][1], a1l[u][1]);
            split_tf32(sigmoid_fast(bB + dot4(sgA, wB)), a1h[u][2], a1l[u][2]);
            split_tf32(sigmoid_fast(bB + dot4(sgB, wB)), a1h[u][3], a1l[u][3]);
          }
        }
        // layer1 (32->32) 3xTF32 mma
        float c1[4][4];
#pragma unroll
        for (int nt = 0; nt < 4; nt++) {
          float2 bi = s->bias1f[nt * 32 + lane];
          c1[nt][0] = bi.x;
          c1[nt][1] = bi.y;
          c1[nt][2] = bi.x;
          c1[nt][3] = bi.y;
#pragma unroll
          for (int u = 0; u < 4; u++) {
            uint4 bf = s->b1f[(u * 4 + nt) * 32 + lane];
            mma8(c1[nt], a1h[u], bf.x, bf.y);
            mma8(c1[nt], a1l[u], bf.x, bf.y);
            mma8(c1[nt], a1h[u], bf.z, bf.w);
          }
        }
        // tanh + C->A + split
        unsigned a2h[4][4], a2l[4][4];
#pragma unroll
        for (int nt = 0; nt < 4; nt++)
#pragma unroll
          for (int j = 0; j < 4; j++) c1[nt][j] = tanh_fast(c1[nt][j]);
#pragma unroll
        for (int u = 0; u < 4; u++) {
          float af[4];
          cvt_c2a_f(c1[u], af, e, s0, s1);
#pragma unroll
          for (int j = 0; j < 4; j++) split_tf32(af[j], a2h[u][j], a2l[u][j]);
        }
        // layer2 (32->32) 3xTF32 mma
        float c2[4][4];
#pragma unroll
        for (int nt = 0; nt < 4; nt++) {
          float2 bi = s->bias2f[nt * 32 + lane];
          c2[nt][0] = bi.x;
          c2[nt][1] = bi.y;
          c2[nt][2] = bi.x;
          c2[nt][3] = bi.y;
#pragma unroll
          for (int u = 0; u < 4; u++) {
            uint4 bf = s->b2f[(u * 4 + nt) * 32 + lane];
            mma8(c2[nt], a2h[u], bf.x, bf.y);
            mma8(c2[nt], a2l[u], bf.x, bf.y);
            mma8(c2[nt], a2h[u], bf.z, bf.w);
          }
        }
        // store G rows
#pragma unroll
        for (int nt = 0; nt < 4; nt++) {
          int colb = nt * 8 + 2 * q;
          int r0r = mt * 16 + g;
          *reinterpret_cast<float2*>(&gbuf[r0r * GSTRIDE + colb]) =
              make_float2(c2[nt][0], c2[nt][1]);
          int r1r = r0r + 8;
          if (r1r < Mm)
            *reinterpret_cast<float2*>(&gbuf[r1r * GSTRIDE + colb]) =
                make_float2(c2[nt][2], c2[nt][3]);
        }
      }
      __syncwarp();
      // bilinear: Bm[l][lane] += R[m][l] * G[m][lane]
      const float4* const rb = R4 + (pair0 + pp) * Mm;
#pragma unroll 6
      for (int m = 0; m < Mm; m++) {
        float gv = gbuf[m * GSTRIDE + lane];
        float4 r = rb[m];
        bm[pp][0] += r.x * gv;
        bm[pp][1] += r.y * gv;
        bm[pp][2] += r.z * gv;
        bm[pp][3] += r.w * gv;
      }
      __syncwarp();  // gbuf reused by next pp
    }

    // D[k][n] = sum_l Bm[l][k] * Bm[l][n] (A = Bm^T identity), STG to Dg
#pragma unroll
    for (int pp = 0; pp < 2; pp++) {
      float* const drow = Dg + (pair0 + pp) * 256;
#pragma unroll
      for (int k = 0; k < 8; k++) {
        float d = 0.f;
#pragma unroll
        for (int l = 0; l < 4; l++) {
          float a = __shfl_sync(FULLM, bm[pp][l], k);
          d += a * bm[pp][l];
        }
        drow[k * 32 + lane] = d;
      }
    }
  }
}

// ======================= Kernel 2: fit MLP (batched mma) ===================

__global__ void __launch_bounds__(THREADS2, 1) fit_kernel(
    const float* __restrict__ Wf0, const float* __restrict__ bf0,
    const float* __restrict__ Wf1, const float* __restrict__ bf1,
    const float* __restrict__ Wf2, const float* __restrict__ bf2,
    const float* __restrict__ Wf3, const float* __restrict__ bf3,
    float* __restrict__ out) {
  extern __shared__ char smraw[];
  Smem2* s = reinterpret_cast<Smem2*>(smraw);
  const int tid = threadIdx.x;

  // B-fragment tables: k-rows r0 = kt*8+q, r1 = r0+4; col = nt*8+g
  for (int i = tid; i < 32 * 8 * 32; i += THREADS2) {
    int L = i & 31, nt = (i >> 5) & 7, kt = i >> 8;
    int q = L & 3, g = L >> 2;
    int r0 = kt * 8 + q, r1 = r0 + 4, c = nt * 8 + g;
    unsigned h0, l0, h1, l1;
    split_tf32(Wf0[r0 * 64 + c], h0, l0);
    split_tf32(Wf0[r1 * 64 + c], h1, l1);
    s->f0[i] = make_uint4(h0, h1, l0, l1);
  }
  for (int i = tid; i < 8 * 8 * 32; i += THREADS2) {
    int L = i & 31, nt = (i >> 5) & 7, kt = i >> 8;
    int q = L & 3, g = L >> 2;
    int r0 = kt * 8 + q, r1 = r0 + 4, c = nt * 8 + g;
    unsigned h0, l0, h1, l1;
    split_tf32(Wf1[r0 * 64 + c], h0, l0);
    split_tf32(Wf1[r1 * 64 + c], h1, l1);
    s->f1[i] = make_uint4(h0, h1, l0, l1);
    split_tf32(Wf2[r0 * 64 + c], h0, l0);
    split_tf32(Wf2[r1 * 64 + c], h1, l1);
    s->f2[i] = make_uint4(h0, h1, l0, l1);
  }
  for (int i = tid; i < 256; i += THREADS2) {
    int nt = i >> 5, q = i & 3;
    s->bias0f[i] = make_float2(bf0[nt * 8 + 2 * q], bf0[nt * 8 + 2 * q + 1]);
    s->bias1f[i] = make_float2(bf1[nt * 8 + 2 * q], bf1[nt * 8 + 2 * q + 1]);
    s->bias2f[i] = make_float2(bf2[nt * 8 + 2 * q], bf2[nt * 8 + 2 * q + 1]);
  }
  if (tid < 64) s->wf3s[tid] = Wf3[tid];
  if (tid == 0) s->bf3s = bf3[0];
  __syncthreads();

  const int lane = tid & 31, wid = tid >> 5;
  const int q = lane & 3, g = lane >> 2;
  const int e = q & 1;
  const int s0 = (lane & ~3) | (q >> 1);
  const int s1 = s0 + 2;

  for (int t = blockIdx.x * WARPS2 + wid; t < NTILES; t += GRID2 * WARPS2) {
    const float* const dgp = Dg + (size_t)t * 16 * 256;

    // ---- fit0: [16 pairs x 256] @ [256 x 64], pairs on M
    float c0[8][4];
#pragma unroll
    for (int nt = 0; nt < 8; nt++) {
      float2 bi = s->bias0f[nt * 32 + lane];
      c0[nt][0] = bi.x;
      c0[nt][1] = bi.y;
      c0[nt][2] = bi.x;
      c0[nt][3] = bi.y;
    }
#pragma unroll 1
    for (int kt = 0; kt < 32; kt++) {
      unsigned ah[4], al[4];
      split_tf32(dgp[g * 256 + kt * 8 + q], ah[0], al[0]);
      split_tf32(dgp[(g + 8) * 256 + kt * 8 + q], ah[1], al[1]);
      split_tf32(dgp[g * 256 + kt * 8 + q + 4], ah[2], al[2]);
      split_tf32(dgp[(g + 8) * 256 + kt * 8 + q + 4], ah[3], al[3]);
#pragma unroll
      for (int nt = 0; nt < 8; nt++) {
        uint4 bf = s->f0[(kt * 8 + nt) * 32 + lane];
        mma8(c0[nt], ah, bf.x, bf.y);
        mma8(c0[nt], al, bf.x, bf.y);
        mma8(c0[nt], ah, bf.z, bf.w);
      }
    }
    // tanh + C->A
    unsigned ah1[8][4], al1[8][4];
#pragma unroll
    for (int nt = 0; nt < 8; nt++)
#pragma unroll
      for (int j = 0; j < 4; j++) c0[nt][j] = tanh_fast(c0[nt][j]);
#pragma unroll
    for (int u = 0; u < 8; u++) {
      float af[4];
      cvt_c2a_f(c0[u], af, e, s0, s1);
#pragma unroll
      for (int j = 0; j < 4; j++) split_tf32(af[j], ah1[u][j], al1[u][j]);
    }

    // ---- fit1: [16 x 64] @ [64 x 64], sigmoid
    float c1[8][4];
#pragma unroll
    for (int nt = 0; nt < 8; nt++) {
      float2 bi = s->bias1f[nt * 32 + lane];
      c1[nt][0] = bi.x;
      c1[nt][1] = bi.y;
      c1[nt][2] = bi.x;
      c1[nt][3] = bi.y;
    }
#pragma unroll 2
    for (int kt = 0; kt < 8; kt++) {
#pragma unroll
      for (int nt = 0; nt < 8; nt++) {
        uint4 bf = s->f1[(kt * 8 + nt) * 32 + lane];
        mma8(c1[nt], ah1[kt], bf.x, bf.y);
        mma8(c1[nt], al1[kt], bf.x, bf.y);
        mma8(c1[nt], ah1[kt], bf.z, bf.w);
      }
    }
#pragma unroll
    for (int nt = 0; nt < 8; nt++)
#pragma unroll
      for (int j = 0; j < 4; j++) c1[nt][j] = sigmoid_fast(c1[nt][j]);
#pragma unroll
    for (int u = 0; u < 8; u++) {
      float af[4];
      cvt_c2a_f(c1[u], af, e, s0, s1);
#pragma unroll
      for (int j = 0; j < 4; j++) split_tf32(af[j], ah1[u][j], al1[u][j]);
    }

    // ---- fit2: [16 x 64] @ [64 x 64], tanh
    float c2[8][4];
#pragma unroll
    for (int nt = 0; nt < 8; nt++) {
      float2 bi = s->bias2f[nt * 32 + lane];
      c2[nt][0] = bi.x;
      c2[nt][1] = bi.y;
      c2[nt][2] = bi.x;
      c2[nt][3] = bi.y;
    }
#pragma unroll 2
    for (int kt = 0; kt < 8; kt++) {
#pragma unroll
      for (int nt = 0; nt < 8; nt++) {
        uint4 bf = s->f2[(kt * 8 + nt) * 32 + lane];
        mma8(c2[nt], ah1[kt], bf.x, bf.y);
        mma8(c2[nt], al1[kt], bf.x, bf.y);
        mma8(c2[nt], ah1[kt], bf.z, bf.w);
      }
    }

    // ---- fit3: 64 -> 1, sum over 16 pairs, atomicAdd mean
    float slo = 0.f, shi = 0.f;
#pragma unroll
    for (int nt = 0; nt < 8; nt++) {
      float wa = s->wf3s[nt * 8 + 2 * q];
      float wb = s->wf3s[nt * 8 + 2 * q + 1];
      slo += tanh_fast(c2[nt][0]) * wa + tanh_fast(c2[nt][1]) * wb;
      shi += tanh_fast(c2[nt][2]) * wa + tanh_fast(c2[nt][3]) * wb;
    }
    float tot = slo + shi;
#pragma unroll
    for (int off = 16; off; off >>= 1) tot += __shfl_xor_sync(FULLM, tot, off);
    if (lane == 0) {
      atomicAdd(out + (t >> 5), (tot + 16.0f * s->bf3s) * (1.0f / 512.0f));
    }
  }
}

extern "C" void kernel_launch(void* const* d_in, const int* in_sizes, int n_in,
                              void* d_out, int out_size) {
  const float* Sg = (const float*)d_in[0];
  const float* R = (const float*)d_in[1];
  const float* We0 = (const float*)d_in[2];
  const float* be0 = (const float*)d_in[3];
  const float* We1 = (const float*)d_in[4];
  const float* be1 = (const float*)d_in[5];
  const float* We2 = (const float*)d_in[6];
  const float* be2 = (const float*)d_in[7];
  const float* Wf0 = (const float*)d_in[8];
  const float* bf0 = (const float*)d_in[9];
  const float* Wf1 = (const float*)d_in[10];
  const float* bf1 = (const float*)d_in[11];
  const float* Wf2 = (const float*)d_in[12];
  const float* bf2 = (const float*)d_in[13];
  const float* Wf3 = (const float*)d_in[14];
  const float* bf3 = (const float*)d_in[15];
  float* out = (float*)d_out;

  (void)in_sizes;
  (void)n_in;

  cudaFuncSetAttribute(emb_kernel, cudaFuncAttributeMaxDynamicSharedMemorySize,
                       (int)sizeof(Smem1));
  cudaFuncSetAttribute(fit_kernel, cudaFuncAttributeMaxDynamicSharedMemorySize,
                       (int)sizeof(Smem2));

  cudaMemsetAsync(out, 0, (size_t)out_size * sizeof(float));

  emb_kernel<<<GRID1, THREADS1, sizeof(Smem1)>>>(Sg, R, We0, be0, We1, be1,
                                                 We2, be2);
  fit_kernel<<<GRID2, THREADS2, sizeof(Smem2)>>>(Wf0, bf0, Wf1, bf1, Wf2, bf2,
                                                 Wf3, bf3, out);
}

// round 8
// speedup vs baseline: 2.6173x; 1.4167x over previous
#include <cuda_runtime.h>
#include <cstdint>

namespace {

constexpr int Mm = 30;
constexpr int NPAIR = 64 * 512;       // 32768
constexpr int NPAIR2 = NPAIR / 2;     // 16384 pair-pairs
constexpr unsigned FULLM = 0xffffffffu;
constexpr int GSTRIDE = 34;

// emb kernel config
constexpr int WARPS1 = 12;
constexpr int THREADS1 = WARPS1 * 32;  // 384
constexpr int GRID1 = 296;             // 2 blocks/SM

// fit kernel config
constexpr int WARPS2 = 8;
constexpr int THREADS2 = WARPS2 * 32;  // 256
constexpr int GRID2 = 296;             // 2 blocks/SM
constexpr int NTILES = NPAIR / 16;     // 2048 (16 pairs per tile)

struct Smem1 {
  uint4  b1f[8 * 32];       // emb layer1 B-frags (b0h,b1h,b0l,b1l), [(u*4+nt)*32+lane]
  uint4  b2f[8 * 32];
  float4 w0colf4[32];
  float2 bias1f[4 * 32];
  float2 bias2f[4 * 32];
  float  be0s[32];
  __align__(16) float gbuf[WARPS1][1024];
};

struct Smem2 {
  uint4  f0[16 * 8 * 32];   // fit0 B-frags [(kt*8+nt)*32+lane]  64 KB
  uint4  f1[4 * 8 * 32];    // 16 KB
  uint4  f2[4 * 8 * 32];    // 16 KB
  float2 bias0f[8 * 32];
  float2 bias1f[8 * 32];
  float2 bias2f[8 * 32];
  float  wf3s[64];
  float  bf3s;
};

__device__ float Dg[NPAIR * 256];  // 32 MB scratch: D matrix

__device__ __forceinline__ float tanh_fast(float x) {
  float y;
  asm("tanh.approx.f32 %0, %1;" : "=f"(y) : "f"(x));
  return y;
}
__device__ __forceinline__ float sigmoid_fast(float x) {
  return 0.5f * tanh_fast(0.5f * x) + 0.5f;
}
__device__ __forceinline__ float dot4(float4 a, float4 b) {
  return a.x * b.x + a.y * b.y + a.z * b.z + a.w * b.w;
}
// pack (x_keven -> lo half, x_kodd -> hi half) as bf16x2
__device__ __forceinline__ unsigned bfpack(float keven, float kodd) {
  unsigned r;
  asm("cvt.rn.bf16x2.f32 %0, %1, %2;" : "=r"(r) : "f"(kodd), "f"(keven));
  return r;
}
// split pair into bf16 hi + bf16 residual-lo packed regs
__device__ __forceinline__ void bfsplit2(float x0, float x1, unsigned& h,
                                         unsigned& l) {
  h = bfpack(x0, x1);
  float h0 = __uint_as_float(h << 16);
  float h1 = __uint_as_float(h & 0xFFFF0000u);
  l = bfpack(x0 - h0, x1 - h1);
}
__device__ __forceinline__ void mma16(float c[4], const unsigned a[4],
                                      unsigned b0, unsigned b1) {
  asm volatile(
      "mma.sync.aligned.m16n8k16.row.col.f32.bf16.bf16.f32 "
      "{%0,%1,%2,%3}, {%4,%5,%6,%7}, {%8,%9}, {%0,%1,%2,%3};"
      : "+f"(c[0]), "+f"(c[1]), "+f"(c[2]), "+f"(c[3])
      : "r"(a[0]), "r"(a[1]), "r"(a[2]), "r"(a[3]), "r"(b0), "r"(b1));
}
// 3-product split-bf16 mma: Ah*Bh + Al*Bh + Ah*Bl
__device__ __forceinline__ void mma3(float c[4], const unsigned ah[4],
                                     const unsigned al[4], uint4 bf) {
  mma16(c, ah, bf.x, bf.y);
  mma16(c, al, bf.x, bf.y);
  mma16(c, ah, bf.z, bf.w);
}
// C-frags of n-tiles (2u, 2u+1) -> A-frag of k-tile u (k16): pure packing.
__device__ __forceinline__ void c2a_pack(const float ce[4], const float co[4],
                                         unsigned ah[4], unsigned al[4]) {
  bfsplit2(ce[0], ce[1], ah[0], al[0]);
  bfsplit2(ce[2], ce[3], ah[1], al[1]);
  bfsplit2(co[0], co[1], ah[2], al[2]);
  bfsplit2(co[2], co[3], ah[3], al[3]);
}

}  // namespace

// ======================= Kernel 1: emb MLP + bilinear -> D =================

__global__ void __launch_bounds__(THREADS1, 2) emb_kernel(
    const float* __restrict__ Sg, const float* __restrict__ R,
    const float* __restrict__ We0, const float* __restrict__ be0,
    const float* __restrict__ We1, const float* __restrict__ be1,
    const float* __restrict__ We2, const float* __restrict__ be2) {
  extern __shared__ char smraw[];
  Smem1* s = reinterpret_cast<Smem1*>(smraw);
  const int tid = threadIdx.x;

  // B-fragment tables (k16): k-rows u*16 + {2q,2q+1,2q+8,2q+9}, col nt*8+g
  for (int i = tid; i < 256; i += THREADS1) {
    int L = i & 31, nt = (i >> 5) & 3, u = i >> 7;
    int q = L & 3, g = L >> 2;
    int r00 = u * 16 + 2 * q, r10 = r00 + 8;
    int c = nt * 8 + g;
    unsigned b0h, b0l, b1h, b1l;
    bfsplit2(We1[r00 * 32 + c], We1[(r00 + 1) * 32 + c], b0h, b0l);
    bfsplit2(We1[r10 * 32 + c], We1[(r10 + 1) * 32 + c], b1h, b1l);
    s->b1f[i] = make_uint4(b0h, b1h, b0l, b1l);
    bfsplit2(We2[r00 * 32 + c], We2[(r00 + 1) * 32 + c], b0h, b0l);
    bfsplit2(We2[r10 * 32 + c], We2[(r10 + 1) * 32 + c], b1h, b1l);
    s->b2f[i] = make_uint4(b0h, b1h, b0l, b1l);
  }
  for (int i = tid; i < 128; i += THREADS1) {
    int t = i >> 5, L = i & 31, q = L & 3;
    s->bias1f[i] = make_float2(be1[t * 8 + 2 * q], be1[t * 8 + 2 * q + 1]);
    s->bias2f[i] = make_float2(be2[t * 8 + 2 * q], be2[t * 8 + 2 * q + 1]);
  }
  if (tid < 32) {
    s->w0colf4[tid] =
        make_float4(We0[tid], We0[32 + tid], We0[64 + tid], We0[96 + tid]);
    s->be0s[tid] = be0[tid];
  }
  __syncthreads();

  const int lane = tid & 31, wid = tid >> 5;
  const int q = lane & 3, g = lane >> 2;

  float* const gbuf = s->gbuf[wid];
  const float4* const Sg4 = reinterpret_cast<const float4*>(Sg);
  const float4* const R4 = reinterpret_cast<const float4*>(R);

  for (int it = blockIdx.x * WARPS1 + wid; it < NPAIR2; it += GRID1 * WARPS1) {
    const int pair0 = it * 2;
    float bm[2][4] = {{0.f, 0.f, 0.f, 0.f}, {0.f, 0.f, 0.f, 0.f}};

#pragma unroll 1
    for (int pp = 0; pp < 2; pp++) {
      const float4* const sgb = Sg4 + (pair0 + pp) * Mm;
#pragma unroll 1
      for (int mt = 0; mt < 2; mt++) {
        // ---- layer0 (4->32, sigmoid) directly into k16 A-fragments
        unsigned a1h[2][4], a1l[2][4];
        {
          int rA = mt * 16 + g;
          int rB = rA + 8;
          float4 sgA = sgb[rA];
          float4 sgB = (rB < Mm) ? sgb[rB] : make_float4(0.f, 0.f, 0.f, 0.f);
#pragma unroll
          for (int u = 0; u < 2; u++) {
            int c0 = u * 16 + 2 * q;    // k even
            int c2 = c0 + 8;
            float4 w0v = s->w0colf4[c0];
            float4 w1v = s->w0colf4[c0 + 1];
            float4 w2v = s->w0colf4[c2];
            float4 w3v = s->w0colf4[c2 + 1];
            float b0v = s->be0s[c0], b1v = s->be0s[c0 + 1];
            float b2v = s->be0s[c2], b3v = s->be0s[c2 + 1];
            bfsplit2(sigmoid_fast(b0v + dot4(sgA, w0v)),
                     sigmoid_fast(b1v + dot4(sgA, w1v)), a1h[u][0], a1l[u][0]);
            bfsplit2(sigmoid_fast(b0v + dot4(sgB, w0v)),
                     sigmoid_fast(b1v + dot4(sgB, w1v)), a1h[u][1], a1l[u][1]);
            bfsplit2(sigmoid_fast(b2v + dot4(sgA, w2v)),
                     sigmoid_fast(b3v + dot4(sgA, w3v)), a1h[u][2], a1l[u][2]);
            bfsplit2(sigmoid_fast(b2v + dot4(sgB, w2v)),
                     sigmoid_fast(b3v + dot4(sgB, w3v)), a1h[u][3], a1l[u][3]);
          }
        }
        // ---- layer1 (32->32): 2 k-tiles x 4 n-tiles x 3 mma
        float c1v[4][4];
#pragma unroll
        for (int nt = 0; nt < 4; nt++) {
          float2 bi = s->bias1f[nt * 32 + lane];
          c1v[nt][0] = bi.x;
          c1v[nt][1] = bi.y;
          c1v[nt][2] = bi.x;
          c1v[nt][3] = bi.y;
#pragma unroll
          for (int u = 0; u < 2; u++)
            mma3(c1v[nt], a1h[u], a1l[u], s->b1f[(u * 4 + nt) * 32 + lane]);
        }
        // ---- tanh + C->A pack (no shuffles with k16)
        unsigned a2h[2][4], a2l[2][4];
#pragma unroll
        for (int nt = 0; nt < 4; nt++)
#pragma unroll
          for (int j = 0; j < 4; j++) c1v[nt][j] = tanh_fast(c1v[nt][j]);
#pragma unroll
        for (int u = 0; u < 2; u++)
          c2a_pack(c1v[2 * u], c1v[2 * u + 1], a2h[u], a2l[u]);
        // ---- layer2 (32->32, linear)
        float c2v[4][4];
#pragma unroll
        for (int nt = 0; nt < 4; nt++) {
          float2 bi = s->bias2f[nt * 32 + lane];
          c2v[nt][0] = bi.x;
          c2v[nt][1] = bi.y;
          c2v[nt][2] = bi.x;
          c2v[nt][3] = bi.y;
#pragma unroll
          for (int u = 0; u < 2; u++)
            mma3(c2v[nt], a2h[u], a2l[u], s->b2f[(u * 4 + nt) * 32 + lane]);
        }
        // ---- store G rows of this m-tile
#pragma unroll
        for (int nt = 0; nt < 4; nt++) {
          int colb = nt * 8 + 2 * q;
          int r0r = mt * 16 + g;
          *reinterpret_cast<float2*>(&gbuf[r0r * GSTRIDE + colb]) =
              make_float2(c2v[nt][0], c2v[nt][1]);
          int r1r = r0r + 8;
          if (r1r < Mm)
            *reinterpret_cast<float2*>(&gbuf[r1r * GSTRIDE + colb]) =
                make_float2(c2v[nt][2], c2v[nt][3]);
        }
      }
      __syncwarp();
      // ---- bilinear: Bm[l][lane] += R[m][l] * G[m][lane]
      const float4* const rb = R4 + (pair0 + pp) * Mm;
#pragma unroll 6
      for (int m = 0; m < Mm; m++) {
        float gv = gbuf[m * GSTRIDE + lane];
        float4 r = rb[m];
        bm[pp][0] += r.x * gv;
        bm[pp][1] += r.y * gv;
        bm[pp][2] += r.z * gv;
        bm[pp][3] += r.w * gv;
      }
      __syncwarp();
    }

    // D[k][n] = sum_l Bm[l][k] * Bm[l][n] (A = Bm^T), STG to Dg
#pragma unroll
    for (int pp = 0; pp < 2; pp++) {
      float* const drow = Dg + (pair0 + pp) * 256;
#pragma unroll
      for (int k = 0; k < 8; k++) {
        float d = 0.f;
#pragma unroll
        for (int l = 0; l < 4; l++) {
          float a = __shfl_sync(FULLM, bm[pp][l], k);
          d += a * bm[pp][l];
        }
        drow[k * 32 + lane] = d;
      }
    }
  }
}

// ======================= Kernel 2: fit MLP (batched bf16 mma) ==============

__global__ void __launch_bounds__(THREADS2, 2) fit_kernel(
    const float* __restrict__ Wf0, const float* __restrict__ bf0,
    const float* __restrict__ Wf1, const float* __restrict__ bf1,
    const float* __restrict__ Wf2, const float* __restrict__ bf2,
    const float* __restrict__ Wf3, const float* __restrict__ bf3,
    float* __restrict__ out) {
  extern __shared__ char smraw[];
  Smem2* s = reinterpret_cast<Smem2*>(smraw);
  const int tid = threadIdx.x;

  for (int i = tid; i < 16 * 8 * 32; i += THREADS2) {
    int L = i & 31, nt = (i >> 5) & 7, kt = i >> 8;
    int q = L & 3, g = L >> 2;
    int r00 = kt * 16 + 2 * q, r10 = r00 + 8;
    int c = nt * 8 + g;
    unsigned b0h, b0l, b1h, b1l;
    bfsplit2(Wf0[r00 * 64 + c], Wf0[(r00 + 1) * 64 + c], b0h, b0l);
    bfsplit2(Wf0[r10 * 64 + c], Wf0[(r10 + 1) * 64 + c], b1h, b1l);
    s->f0[i] = make_uint4(b0h, b1h, b0l, b1l);
  }
  for (int i = tid; i < 4 * 8 * 32; i += THREADS2) {
    int L = i & 31, nt = (i >> 5) & 7, kt = i >> 8;
    int q = L & 3, g = L >> 2;
    int r00 = kt * 16 + 2 * q, r10 = r00 + 8;
    int c = nt * 8 + g;
    unsigned b0h, b0l, b1h, b1l;
    bfsplit2(Wf1[r00 * 64 + c], Wf1[(r00 + 1) * 64 + c], b0h, b0l);
    bfsplit2(Wf1[r10 * 64 + c], Wf1[(r10 + 1) * 64 + c], b1h, b1l);
    s->f1[i] = make_uint4(b0h, b1h, b0l, b1l);
    bfsplit2(Wf2[r00 * 64 + c], Wf2[(r00 + 1) * 64 + c], b0h, b0l);
    bfsplit2(Wf2[r10 * 64 + c], Wf2[(r10 + 1) * 64 + c], b1h, b1l);
    s->f2[i] = make_uint4(b0h, b1h, b0l, b1l);
  }
  for (int i = tid; i < 256; i += THREADS2) {
    int nt = i >> 5, q = i & 3;
    s->bias0f[i] = make_float2(bf0[nt * 8 + 2 * q], bf0[nt * 8 + 2 * q + 1]);
    s->bias1f[i] = make_float2(bf1[nt * 8 + 2 * q], bf1[nt * 8 + 2 * q + 1]);
    s->bias2f[i] = make_float2(bf2[nt * 8 + 2 * q], bf2[nt * 8 + 2 * q + 1]);
  }
  if (tid < 64) s->wf3s[tid] = Wf3[tid];
  if (tid == 0) s->bf3s = bf3[0];
  __syncthreads();

  const int lane = tid & 31, wid = tid >> 5;
  const int q = lane & 3, g = lane >> 2;

  for (int t = blockIdx.x * WARPS2 + wid; t < NTILES; t += GRID2 * WARPS2) {
    const float* const dgp = Dg + (size_t)t * 16 * 256;

    // ---- fit0: [16 pairs x 256] @ [256 x 64]
    float c0[8][4];
#pragma unroll
    for (int nt = 0; nt < 8; nt++) {
      float2 bi = s->bias0f[nt * 32 + lane];
      c0[nt][0] = bi.x;
      c0[nt][1] = bi.y;
      c0[nt][2] = bi.x;
      c0[nt][3] = bi.y;
    }
#pragma unroll 1
    for (int kt = 0; kt < 16; kt++) {
      unsigned ah[4], al[4];
      float2 d00 = *reinterpret_cast<const float2*>(
          &dgp[g * 256 + kt * 16 + 2 * q]);
      float2 d01 = *reinterpret_cast<const float2*>(
          &dgp[(g + 8) * 256 + kt * 16 + 2 * q]);
      float2 d10 = *reinterpret_cast<const float2*>(
          &dgp[g * 256 + kt * 16 + 8 + 2 * q]);
      float2 d11 = *reinterpret_cast<const float2*>(
          &dgp[(g + 8) * 256 + kt * 16 + 8 + 2 * q]);
      bfsplit2(d00.x, d00.y, ah[0], al[0]);
      bfsplit2(d01.x, d01.y, ah[1], al[1]);
      bfsplit2(d10.x, d10.y, ah[2], al[2]);
      bfsplit2(d11.x, d11.y, ah[3], al[3]);
#pragma unroll
      for (int nt = 0; nt < 8; nt++)
        mma3(c0[nt], ah, al, s->f0[(kt * 8 + nt) * 32 + lane]);
    }
    // tanh + C->A pack
    unsigned ah1[4][4], al1[4][4];
#pragma unroll
    for (int nt = 0; nt < 8; nt++)
#pragma unroll
      for (int j = 0; j < 4; j++) c0[nt][j] = tanh_fast(c0[nt][j]);
#pragma unroll
    for (int u = 0; u < 4; u++)
      c2a_pack(c0[2 * u], c0[2 * u + 1], ah1[u], al1[u]);

    // ---- fit1: [16 x 64] @ [64 x 64], sigmoid
    float c1[8][4];
#pragma unroll
    for (int nt = 0; nt < 8; nt++) {
      float2 bi = s->bias1f[nt * 32 + lane];
      c1[nt][0] = bi.x;
      c1[nt][1] = bi.y;
      c1[nt][2] = bi.x;
      c1[nt][3] = bi.y;
    }
#pragma unroll 2
    for (int kt = 0; kt < 4; kt++)
#pragma unroll
      for (int nt = 0; nt < 8; nt++)
        mma3(c1[nt], ah1[kt], al1[kt], s->f1[(kt * 8 + nt) * 32 + lane]);
#pragma unroll
    for (int nt = 0; nt < 8; nt++)
#pragma unroll
      for (int j = 0; j < 4; j++) c1[nt][j] = sigmoid_fast(c1[nt][j]);
#pragma unroll
    for (int u = 0; u < 4; u++)
      c2a_pack(c1[2 * u], c1[2 * u + 1], ah1[u], al1[u]);

    // ---- fit2: [16 x 64] @ [64 x 64], tanh
    float c2[8][4];
#pragma unroll
    for (int nt = 0; nt < 8; nt++) {
      float2 bi = s->bias2f[nt * 32 + lane];
      c2[nt][0] = bi.x;
      c2[nt][1] = bi.y;
      c2[nt][2] = bi.x;
      c2[nt][3] = bi.y;
    }
#pragma unroll 2
    for (int kt = 0; kt < 4; kt++)
#pragma unroll
      for (int nt = 0; nt < 8; nt++)
        mma3(c2[nt], ah1[kt], al1[kt], s->f2[(kt * 8 + nt) * 32 + lane]);

    // ---- fit3: 64 -> 1, sum over 16 pairs, atomicAdd mean
    float slo = 0.f, shi = 0.f;
#pragma unroll
    for (int nt = 0; nt < 8; nt++) {
      float wa = s->wf3s[nt * 8 + 2 * q];
      float wb = s->wf3s[nt * 8 + 2 * q + 1];
      slo += tanh_fast(c2[nt][0]) * wa + tanh_fast(c2[nt][1]) * wb;
      shi += tanh_fast(c2[nt][2]) * wa + tanh_fast(c2[nt][3]) * wb;
    }
    float tot = slo + shi;
#pragma unroll
    for (int off = 16; off; off >>= 1) tot += __shfl_xor_sync(FULLM, tot, off);
    if (lane == 0) {
      atomicAdd(out + (t >> 5), (tot + 16.0f * s->bf3s) * (1.0f / 512.0f));
    }
  }
}

extern "C" void kernel_launch(void* const* d_in, const int* in_sizes, int n_in,
                              void* d_out, int out_size) {
  const float* Sg = (const float*)d_in[0];
  const float* R = (const float*)d_in[1];
  const float* We0 = (const float*)d_in[2];
  const float* be0 = (const float*)d_in[3];
  const float* We1 = (const float*)d_in[4];
  const float* be1 = (const float*)d_in[5];
  const float* We2 = (const float*)d_in[6];
  const float* be2 = (const float*)d_in[7];
  const float* Wf0 = (const float*)d_in[8];
  const float* bf0 = (const float*)d_in[9];
  const float* Wf1 = (const float*)d_in[10];
  const float* bf1 = (const float*)d_in[11];
  const float* Wf2 = (const float*)d_in[12];
  const float* bf2 = (const float*)d_in[13];
  const float* Wf3 = (const float*)d_in[14];
  const float* bf3 = (const float*)d_in[15];
  float* out = (float*)d_out;

  (void)in_sizes;
  (void)n_in;

  cudaFuncSetAttribute(emb_kernel, cudaFuncAttributeMaxDynamicSharedMemorySize,
                       (int)sizeof(Smem1));
  cudaFuncSetAttribute(fit_kernel, cudaFuncAttributeMaxDynamicSharedMemorySize,
                       (int)sizeof(Smem2));

  cudaMemsetAsync(out, 0, (size_t)out_size * sizeof(float));

  emb_kernel<<<GRID1, THREADS1, sizeof(Smem1)>>>(Sg, R, We0, be0, We1, be1,
                                                 We2, be2);
  fit_kernel<<<GRID2, THREADS2, sizeof(Smem2)>>>(Wf0, bf0, Wf1, bf1, Wf2, bf2,
                                                 Wf3, bf3, out);
}